// round 6
// baseline (speedup 1.0000x reference)
#include <cuda_runtime.h>
#include <cuda_fp16.h>
#include <cstdint>

#define BQ   256
#define NTOK 196
#define NTOT 197
#define DIM  768
#define DTXT 512
#define TTOT (BQ*NTOK)

__device__ float g_attn[(size_t)BQ*NTOK*NTOK];
__device__ float g_buf1[(size_t)TTOT*DIM];
__device__ float g_buf2[(size_t)TTOT*DIM];
__device__ float g_txt [(size_t)BQ*DIM];
__device__ float g_tq  [(size_t)BQ*DIM];

__device__ __forceinline__ float gelu_exact(float x) { return x * normcdff(x); }

__device__ __forceinline__ uint32_t packh2(float a, float b) {
    __half2 h = __floats2half2_rn(a, b);   // lo = a, hi = b
    return *reinterpret_cast<uint32_t*>(&h);
}
// swizzle bits for a [row][16 u32] tile (u32 = half2 k-pair)
__device__ __forceinline__ int swbits(int r) {
    return (((r >> 1) & 3) << 2) | ((r >> 3) & 3);
}
__device__ __forceinline__ int swz(int r, int k) { return r*16 + (k ^ swbits(r)); }

// =====================================================================
// fp16 mma.sync GEMM (m16n8k16, fp32 accum), 128x128x32 tile, 8 warps,
// warp tile 64x32, double-buffered smem + register prefetch.
// Tiles stored as u32 half2-pairs, swizzled, conflict-free.
//   BT=false: B is KxN (NN).  BT=true: B is NxK (NT).
// MODE 0: C=alpha*acc   MODE 1: C=gelu(acc+bias)
// MODE 3: out[remap]=resid[remap]+g*(acc+bias)
// =====================================================================
template<int MODE, bool BT>
__launch_bounds__(256, 2)
__global__ void mma_gemm(const float* __restrict__ A, long aBS, int lda,
                         const float* __restrict__ B, long bBS, int ldb,
                         float* __restrict__ C, long cBS, int ldc,
                         int M, int N, int K, float alpha,
                         const float* __restrict__ bias,
                         const float* __restrict__ resid,
                         const float* __restrict__ gscale)
{
    __shared__ uint32_t As[2][128*16];   // 128 rows x 32 k-halves (8KB/buf)
    __shared__ uint32_t Bs[2][128*16];

    const int tid  = threadIdx.x;
    const int lane = tid & 31;
    const int wid  = tid >> 5;
    const int wm   = wid & 1;
    const int wn   = wid >> 1;
    const int m0   = blockIdx.y * 128;
    const int n0   = blockIdx.x * 128;

    const float* Ab = A + (long)blockIdx.z * aBS;
    const float* Bb = B + (long)blockIdx.z * bBS;

    float acc[4][4][4];
    #pragma unroll
    for (int i = 0; i < 4; i++)
        #pragma unroll
        for (int j = 0; j < 4; j++)
            #pragma unroll
            for (int r = 0; r < 4; r++) acc[i][j][r] = 0.f;

    // row-mode loader (A always; B when BT): row rw_r, u32-col base rw_kb
    const int rw_r  = tid >> 1;
    const int rw_kb = (tid & 1) * 8;        // u32 cols 0..7 / 8..15
    const int stg   = rw_kb >> 1;           // 0 or 4: de-conflict stagger
    // column-mode loader (B when NN)
    const int cl_n  = tid & 127;
    const int cl_kh = (tid >> 7) * 8;       // u32 cols

    uint32_t pA[8], pB[8];

    auto loadA = [&](int k0) {
        const int gm = m0 + rw_r, gk = k0 + rw_kb*2;   // float col
        if (gm < M && gk + 15 < K) {
            const float4* p = reinterpret_cast<const float4*>(Ab + (long)gm*lda + gk);
            #pragma unroll
            for (int q = 0; q < 4; q++) {
                float4 v = p[q];
                pA[2*q]   = packh2(v.x, v.y);
                pA[2*q+1] = packh2(v.z, v.w);
            }
        } else {
            #pragma unroll
            for (int q = 0; q < 8; q++) {
                float e0 = (gm < M && gk+2*q   < K) ? Ab[(long)gm*lda + gk+2*q]   : 0.f;
                float e1 = (gm < M && gk+2*q+1 < K) ? Ab[(long)gm*lda + gk+2*q+1] : 0.f;
                pA[q] = packh2(e0, e1);
            }
        }
    };
    auto loadB = [&](int k0) {
        if (BT) {
            const int gn = n0 + rw_r, gk = k0 + rw_kb*2;
            if (gn < N && gk + 15 < K) {
                const float4* p = reinterpret_cast<const float4*>(Bb + (long)gn*ldb + gk);
                #pragma unroll
                for (int q = 0; q < 4; q++) {
                    float4 v = p[q];
                    pB[2*q]   = packh2(v.x, v.y);
                    pB[2*q+1] = packh2(v.z, v.w);
                }
            } else {
                #pragma unroll
                for (int q = 0; q < 8; q++) {
                    float e0 = (gn < N && gk+2*q   < K) ? Bb[(long)gn*ldb + gk+2*q]   : 0.f;
                    float e1 = (gn < N && gk+2*q+1 < K) ? Bb[(long)gn*ldb + gk+2*q+1] : 0.f;
                    pB[q] = packh2(e0, e1);
                }
            }
        } else {
            const int gn = n0 + cl_n;
            const bool nok = gn < N;
            const int gkb = k0 + cl_kh*2;
            #pragma unroll
            for (int q = 0; q < 8; q++) {
                float e0 = (nok && gkb+2*q   < K) ? Bb[(long)(gkb+2*q)  *ldb + gn] : 0.f;
                float e1 = (nok && gkb+2*q+1 < K) ? Bb[(long)(gkb+2*q+1)*ldb + gn] : 0.f;
                pB[q] = packh2(e0, e1);
            }
        }
    };
    auto storeA = [&](int buf) {
        #pragma unroll
        for (int p = 0; p < 8; p++) {
            const int q = p ^ stg;
            As[buf][swz(rw_r, rw_kb + q)] = pA[q];
        }
    };
    auto storeB = [&](int buf) {
        if (BT) {
            #pragma unroll
            for (int p = 0; p < 8; p++) {
                const int q = p ^ stg;
                Bs[buf][swz(rw_r, rw_kb + q)] = pB[q];
            }
        } else {
            #pragma unroll
            for (int q = 0; q < 8; q++)
                Bs[buf][swz(cl_n, cl_kh + q)] = pB[q];
        }
    };

    loadA(0); loadB(0);
    storeA(0); storeB(0);
    __syncthreads();

    // precomputed fragment-read bases: e = row*16 + (c ^ swbits(row));
    // in-loop index = e ^ kb ^ dc  (kb in {0,8}, dc in {0,4}; low-4-bit XOR safe)
    const int g = lane >> 2, c = lane & 3;
    int eA0[4], eA1[4], eB[4];
    #pragma unroll
    for (int i = 0; i < 4; i++) {
        const int r0 = wm*64 + i*16 + g;
        const int r1 = r0 + 8;
        eA0[i] = r0*16 + (c ^ swbits(r0));
        eA1[i] = r1*16 + (c ^ swbits(r1));
    }
    #pragma unroll
    for (int j = 0; j < 4; j++) {
        const int rn = wn*32 + j*8 + g;
        eB[j] = rn*16 + (c ^ swbits(rn));
    }

    int cur = 0;
    for (int k0 = 0; k0 < K; k0 += 32) {
        const bool has_next = (k0 + 32) < K;
        if (has_next) { loadA(k0 + 32); loadB(k0 + 32); }

        #pragma unroll
        for (int ks = 0; ks < 2; ks++) {
            const int kb = ks * 8;
            uint32_t af[4][4];
            #pragma unroll
            for (int i = 0; i < 4; i++) {
                af[i][0] = As[cur][eA0[i] ^ kb];
                af[i][1] = As[cur][eA1[i] ^ kb];
                af[i][2] = As[cur][eA0[i] ^ kb ^ 4];
                af[i][3] = As[cur][eA1[i] ^ kb ^ 4];
            }
            uint32_t bf[4][2];
            #pragma unroll
            for (int j = 0; j < 4; j++) {
                bf[j][0] = Bs[cur][eB[j] ^ kb];
                bf[j][1] = Bs[cur][eB[j] ^ kb ^ 4];
            }
            #pragma unroll
            for (int i = 0; i < 4; i++)
                #pragma unroll
                for (int j = 0; j < 4; j++) {
                    asm volatile(
                        "mma.sync.aligned.m16n8k16.row.col.f32.f16.f16.f32 "
                        "{%0,%1,%2,%3}, {%4,%5,%6,%7}, {%8,%9}, {%0,%1,%2,%3};\n"
                        : "+f"(acc[i][j][0]), "+f"(acc[i][j][1]),
                          "+f"(acc[i][j][2]), "+f"(acc[i][j][3])
                        : "r"(af[i][0]), "r"(af[i][1]), "r"(af[i][2]), "r"(af[i][3]),
                          "r"(bf[j][0]), "r"(bf[j][1]));
                }
        }

        if (has_next) { storeA(cur ^ 1); storeB(cur ^ 1); }
        __syncthreads();
        cur ^= 1;
    }

    const float gsc = (MODE == 3) ? gscale[0] : 0.f;
    const int tg = lane & 3;
    #pragma unroll
    for (int i = 0; i < 4; i++) {
        const int rowB = m0 + wm*64 + i*16;
        #pragma unroll
        for (int j = 0; j < 4; j++) {
            const int colB = n0 + wn*32 + j*8 + tg*2;
            #pragma unroll
            for (int r = 0; r < 4; r++) {
                const int row = rowB + g + ((r >= 2) ? 8 : 0);
                const int col = colB + (r & 1);
                if (row >= M || col >= N) continue;
                float v = acc[i][j][r];
                if (MODE == 0) v *= alpha;
                if (MODE >= 1) v += bias[col];
                if (MODE == 1) v = gelu_exact(v);
                if (MODE == 3) {
                    const int b  = row / NTOK;
                    const int rr = row - b * NTOK;
                    const long off = ((long)b * NTOT + 1 + rr) * DIM + col;
                    C[off] = resid[off] + gsc * v;
                } else {
                    C[(long)blockIdx.z * cBS + (long)row * ldc + col] = v;
                }
            }
        }
    }
}

// ---------------- SIMT fp32 GEMM (tiny text-branch) --------------------------
template<int MODE>
__launch_bounds__(256)
__global__ void gemm_kernel(const float* __restrict__ A, int lda,
                            const float* __restrict__ B, int ldb,
                            float* __restrict__ C, int ldc,
                            int M, int N, int K,
                            const float* __restrict__ bias)
{
    const int BM = 64, BN = 64, BK = 16;
    __shared__ float Ast[BK][BM + 4];
    __shared__ float Bst[BK][BN];
    const int tid = threadIdx.x;
    const int tx = tid & 15, ty = tid >> 4;
    const int m0 = blockIdx.y * BM, n0 = blockIdx.x * BN;
    float acc[4][4] = {};
    const int aRow = tid >> 2, aCol = (tid & 3) * 4;

    for (int k0 = 0; k0 < K; k0 += BK) {
        {
            float4 v = make_float4(0.f,0.f,0.f,0.f);
            int gr = m0 + aRow;
            if (gr < M) {
                int gc = k0 + aCol;
                if (gc + 3 < K) v = *reinterpret_cast<const float4*>(A + (long)gr*lda + gc);
                else {
                    v.x=(gc<K)?A[(long)gr*lda+gc]:0.f;   v.y=(gc+1<K)?A[(long)gr*lda+gc+1]:0.f;
                    v.z=(gc+2<K)?A[(long)gr*lda+gc+2]:0.f; v.w=(gc+3<K)?A[(long)gr*lda+gc+3]:0.f;
                }
            }
            Ast[aCol+0][aRow]=v.x; Ast[aCol+1][aRow]=v.y;
            Ast[aCol+2][aRow]=v.z; Ast[aCol+3][aRow]=v.w;
        }
        {
            int br = tid >> 4, bc = (tid & 15) * 4;
            float4 v = make_float4(0.f,0.f,0.f,0.f);
            int gk = k0 + br, gn = n0 + bc;
            if (gk < K && gn + 3 < N)
                v = *reinterpret_cast<const float4*>(B + (long)gk*ldb + gn);
            *reinterpret_cast<float4*>(&Bst[br][bc]) = v;
        }
        __syncthreads();
        #pragma unroll
        for (int k = 0; k < BK; k++) {
            float4 av = *reinterpret_cast<const float4*>(&Ast[k][ty*4]);
            float4 bv = *reinterpret_cast<const float4*>(&Bst[k][tx*4]);
            acc[0][0]+=av.x*bv.x; acc[0][1]+=av.x*bv.y; acc[0][2]+=av.x*bv.z; acc[0][3]+=av.x*bv.w;
            acc[1][0]+=av.y*bv.x; acc[1][1]+=av.y*bv.y; acc[1][2]+=av.y*bv.z; acc[1][3]+=av.y*bv.w;
            acc[2][0]+=av.z*bv.x; acc[2][1]+=av.z*bv.y; acc[2][2]+=av.z*bv.z; acc[2][3]+=av.z*bv.w;
            acc[3][0]+=av.w*bv.x; acc[3][1]+=av.w*bv.y; acc[3][2]+=av.w*bv.z; acc[3][3]+=av.w*bv.w;
        }
        __syncthreads();
    }
    #pragma unroll
    for (int i = 0; i < 4; i++) {
        int m = m0 + ty*4 + i; if (m >= M) continue;
        #pragma unroll
        for (int j = 0; j < 4; j++) {
            int n = n0 + tx*4 + j; if (n >= N) continue;
            float v = acc[i][j] + bias[n];
            if (MODE == 1) v = gelu_exact(v);
            C[(long)m*ldc + n] = v;
        }
    }
}

__global__ void softmax_kernel(float* __restrict__ S)
{
    int warp = (blockIdx.x * blockDim.x + threadIdx.x) >> 5;
    int lane = threadIdx.x & 31;
    if (warp >= (int)(BQ * NTOK)) return;
    float* p = S + (long)warp * NTOK;
    float v[7], mx = -3.0e38f;
    #pragma unroll
    for (int it = 0; it < 7; it++) {
        int j = lane + it*32;
        v[it] = (j < NTOK) ? p[j] : -3.0e38f;
        mx = fmaxf(mx, v[it]);
    }
    #pragma unroll
    for (int o = 16; o; o >>= 1) mx = fmaxf(mx, __shfl_xor_sync(0xffffffffu, mx, o));
    float s = 0.f;
    #pragma unroll
    for (int it = 0; it < 7; it++) {
        int j = lane + it*32;
        if (j < NTOK) { v[it] = expf(v[it]-mx); s += v[it]; } else v[it] = 0.f;
    }
    #pragma unroll
    for (int o = 16; o; o >>= 1) s += __shfl_xor_sync(0xffffffffu, s, o);
    float inv = 1.f / s;
    #pragma unroll
    for (int it = 0; it < 7; it++) {
        int j = lane + it*32;
        if (j < NTOK) p[j] = v[it]*inv;
    }
}

__global__ void layernorm_kernel(float* __restrict__ X,
                                 const float* __restrict__ w,
                                 const float* __restrict__ b)
{
    int row = blockIdx.x;
    float* p = X + (long)row * DIM;
    float s = 0.f, sq = 0.f;
    for (int j = threadIdx.x; j < DIM; j += blockDim.x) {
        float x = p[j]; s += x; sq += x*x;
    }
    __shared__ float rs[32], rq[32];
    int lane = threadIdx.x & 31, wd = threadIdx.x >> 5;
    #pragma unroll
    for (int o = 16; o; o >>= 1) {
        s  += __shfl_xor_sync(0xffffffffu, s, o);
        sq += __shfl_xor_sync(0xffffffffu, sq, o);
    }
    if (lane == 0) { rs[wd] = s; rq[wd] = sq; }
    __syncthreads();
    int nw = blockDim.x >> 5;
    if (wd == 0) {
        float a = (lane < nw) ? rs[lane] : 0.f;
        float cc = (lane < nw) ? rq[lane] : 0.f;
        #pragma unroll
        for (int o = 16; o; o >>= 1) {
            a  += __shfl_xor_sync(0xffffffffu, a, o);
            cc += __shfl_xor_sync(0xffffffffu, cc, o);
        }
        if (lane == 0) { rs[0] = a; rq[0] = cc; }
    }
    __syncthreads();
    float mu = rs[0] / DIM;
    float var = rq[0] / DIM - mu*mu;
    float rstd = rsqrtf(var + 1e-5f);
    for (int j = threadIdx.x; j < DIM; j += blockDim.x)
        p[j] = (p[j]-mu)*rstd*w[j] + b[j];
}

__global__ void mask_refine_kernel(float* __restrict__ out,
                                   const float* __restrict__ tq,
                                   const float* __restrict__ gamma)
{
    int warp = (blockIdx.x * blockDim.x + threadIdx.x) >> 5;
    int lane = threadIdx.x & 31;
    if (warp >= (int)TTOT) return;
    int b = warp / NTOK, r = warp - b*NTOK;
    float* p = out + ((long)b*NTOT + 1 + r)*DIM;
    const float* t = tq + (long)b*DIM;
    float d = 0.f;
    for (int j = lane; j < DIM; j += 32) d += p[j]*t[j];
    #pragma unroll
    for (int o = 16; o; o >>= 1) d += __shfl_xor_sync(0xffffffffu, d, o);
    float sc = 1.f + gamma[0] / (1.f + expf(-d));
    for (int j = lane; j < DIM; j += 32) p[j] *= sc;
}

__global__ void copy_cls_kernel(const float* __restrict__ img, float* __restrict__ out)
{
    long base = (long)blockIdx.x * NTOT * DIM;
    for (int j = threadIdx.x; j < DIM; j += blockDim.x)
        out[base + j] = img[base + j];
}

// =====================================================================
extern "C" void kernel_launch(void* const* d_in, const int* in_sizes, int n_in,
                              void* d_out, int out_size)
{
    const float* img       = (const float*)d_in[0];
    const float* text      = (const float*)d_in[1];
    const float* w1_msg    = (const float*)d_in[2];
    const float* b1_msg    = (const float*)d_in[3];
    const float* w2_msg    = (const float*)d_in[4];
    const float* b2_msg    = (const float*)d_in[5];
    const float* gamma_gcn = (const float*)d_in[6];
    const float* w1_txt    = (const float*)d_in[7];
    const float* b1_txt    = (const float*)d_in[8];
    const float* w2_txt    = (const float*)d_in[9];
    const float* b2_txt    = (const float*)d_in[10];
    const float* ln_w      = (const float*)d_in[11];
    const float* ln_b      = (const float*)d_in[12];
    const float* gamma     = (const float*)d_in[13];
    float* out = (float*)d_out;

    float *attn, *buf1, *buf2, *txt, *tq;
    cudaGetSymbolAddress((void**)&attn, g_attn);
    cudaGetSymbolAddress((void**)&buf1, g_buf1);
    cudaGetSymbolAddress((void**)&buf2, g_buf2);
    cudaGetSymbolAddress((void**)&txt,  g_txt);
    cudaGetSymbolAddress((void**)&tq,   g_tq);

    const float inv_sqrt_d = 0.03608439182435161f;
    const float* x = img + DIM;

    copy_cls_kernel<<<BQ, 256>>>(img, out);

    mma_gemm<0, true><<<dim3(2, 2, BQ), 256>>>(
        x, (long)NTOT*DIM, DIM, x, (long)NTOT*DIM, DIM,
        attn, (long)NTOK*NTOK, NTOK,
        NTOK, NTOK, DIM, inv_sqrt_d, nullptr, nullptr, nullptr);

    softmax_kernel<<<(TTOT*32 + 255)/256, 256>>>(attn);

    mma_gemm<0, false><<<dim3(6, 2, BQ), 256>>>(
        attn, (long)NTOK*NTOK, NTOK, x, (long)NTOT*DIM, DIM,
        buf1, (long)NTOK*DIM, DIM,
        NTOK, DIM, NTOK, 1.f, nullptr, nullptr, nullptr);

    mma_gemm<1, false><<<dim3(6, TTOT/128, 1), 256>>>(
        buf1, 0, DIM, w1_msg, 0, DIM, buf2, 0, DIM,
        TTOT, DIM, DIM, 1.f, b1_msg, nullptr, nullptr);

    mma_gemm<3, false><<<dim3(6, TTOT/128, 1), 256>>>(
        buf2, 0, DIM, w2_msg, 0, DIM, out, 0, 0,
        TTOT, DIM, DIM, 1.f, b2_msg, img, gamma_gcn);

    gemm_kernel<1><<<dim3(12, 4, 1), 256>>>(
        text, DTXT, w1_txt, DIM, txt, DIM, BQ, DIM, DTXT, b1_txt);
    gemm_kernel<2><<<dim3(12, 4, 1), 256>>>(
        txt, DIM, w2_txt, DIM, tq, DIM, BQ, DIM, DIM, b2_txt);
    layernorm_kernel<<<BQ, 256>>>(tq, ln_w, ln_b);

    mask_refine_kernel<<<(TTOT*32 + 255)/256, 256>>>(out, tq, gamma);
}

// round 7
// speedup vs baseline: 1.3437x; 1.3437x over previous
#include <cuda_runtime.h>
#include <cuda_fp16.h>
#include <cstdint>

#define BQ   256
#define NTOK 196
#define NTOT 197
#define DIM  768
#define DTXT 512
#define TTOT (BQ*NTOK)
#define KPAD 224          // NTOK padded to multiple of 32

// ---------------- scratch (device globals) ----------------
__device__ float  g_attn [(size_t)BQ*NTOK*NTOK];   // f32 scores
__device__ __half g_attnh[(size_t)BQ*NTOK*KPAD];   // softmax(A), half, K-padded
__device__ __half g_xh  [(size_t)TTOT*DIM];        // x tokens, half
__device__ __half g_xT  [(size_t)BQ*DIM*KPAD];     // x^T per batch, half, padded
__device__ __half g_w1T [(size_t)DIM*DIM];
__device__ __half g_w2T [(size_t)DIM*DIM];
__device__ __half g_b1h [(size_t)TTOT*DIM];        // msg (half)
__device__ __half g_b2h [(size_t)TTOT*DIM];        // gelu(h) (half)
__device__ float  g_txt [(size_t)BQ*DIM];
__device__ float  g_tq  [(size_t)BQ*DIM];

__device__ __forceinline__ float gelu_exact(float x) { return x * normcdff(x); }

// swizzle bits for a [row][16 u32] tile (u32 = half2 k-pair)
__device__ __forceinline__ int swbits(int r) {
    return (((r >> 1) & 3) << 2) | ((r >> 3) & 3);
}
__device__ __forceinline__ int swz(int r, int k) { return r*16 + (k ^ swbits(r)); }

// =====================================================================
// fp16 NT GEMM (m16n8k16, fp32 accum): C = alpha * A(MxK) * B(NxK)^T
// A, B row-major half, K-contiguous, K % 32 == 0, rows 16B-aligned.
// 128x128x32 tile, 8 warps, warp tile 64x32, double-buffered smem,
// register prefetch. Row guards only (no K guards).
// MODE 0: f32 C = alpha*acc
// MODE 1: half C = gelu(acc+bias)
// MODE 2: half C = acc
// MODE 3: f32 out[remap] = resid[remap] + g*(acc+bias)
// =====================================================================
template<int MODE>
__launch_bounds__(256, 2)
__global__ void hgemm_nt(const __half* __restrict__ A, long aBS, int lda,
                         const __half* __restrict__ B, long bBS, int ldb,
                         void* __restrict__ Cv, long cBS, int ldc,
                         int M, int N, int K, float alpha,
                         const float* __restrict__ bias,
                         const float* __restrict__ resid,
                         const float* __restrict__ gscale)
{
    __shared__ uint32_t As[2][128*16];   // 128 rows x 16 u32 (32 halves)
    __shared__ uint32_t Bs[2][128*16];

    const int tid  = threadIdx.x;
    const int lane = tid & 31;
    const int wid  = tid >> 5;
    const int wm   = wid & 1;
    const int wn   = wid >> 1;
    const int m0   = blockIdx.y * 128;
    const int n0   = blockIdx.x * 128;

    const __half* Ab = A + (long)blockIdx.z * aBS;
    const __half* Bb = B + (long)blockIdx.z * bBS;

    float acc[4][4][4];
    #pragma unroll
    for (int i = 0; i < 4; i++)
        #pragma unroll
        for (int j = 0; j < 4; j++)
            #pragma unroll
            for (int r = 0; r < 4; r++) acc[i][j][r] = 0.f;

    // loader geometry: thread covers row rw_r, u32 cols rw_kb..rw_kb+7
    const int rw_r  = tid >> 1;
    const int rw_kb = (tid & 1) * 8;        // u32 col base (0 or 8)
    const int kb_h  = (tid & 1) * 16;       // half col base
    const int stg   = (tid & 1) * 4;        // store stagger

    uint4 rA[2], rB[2];
    const uint4 zero4 = make_uint4(0u,0u,0u,0u);

    auto loadA = [&](int k0) {
        const bool ok = (m0 + rw_r) < M;
        const __half* p = Ab + (long)(m0 + rw_r)*lda + k0 + kb_h;
        rA[0] = ok ? *reinterpret_cast<const uint4*>(p)     : zero4;
        rA[1] = ok ? *reinterpret_cast<const uint4*>(p + 8) : zero4;
    };
    auto loadB = [&](int k0) {
        const bool ok = (n0 + rw_r) < N;
        const __half* p = Bb + (long)(n0 + rw_r)*ldb + k0 + kb_h;
        rB[0] = ok ? *reinterpret_cast<const uint4*>(p)     : zero4;
        rB[1] = ok ? *reinterpret_cast<const uint4*>(p + 8) : zero4;
    };
    auto storeA = [&](int buf) {
        const uint32_t* a32 = reinterpret_cast<const uint32_t*>(rA);
        #pragma unroll
        for (int p = 0; p < 8; p++) {
            const int q = p ^ stg;
            As[buf][swz(rw_r, rw_kb + q)] = a32[q];
        }
    };
    auto storeB = [&](int buf) {
        const uint32_t* b32 = reinterpret_cast<const uint32_t*>(rB);
        #pragma unroll
        for (int p = 0; p < 8; p++) {
            const int q = p ^ stg;
            Bs[buf][swz(rw_r, rw_kb + q)] = b32[q];
        }
    };

    loadA(0); loadB(0);
    storeA(0); storeB(0);
    __syncthreads();

    // fragment-read bases (R5/R6-validated): index = e ^ kb ^ dc
    const int g = lane >> 2, c = lane & 3;
    int eA0[4], eA1[4], eB[4];
    #pragma unroll
    for (int i = 0; i < 4; i++) {
        const int r0 = wm*64 + i*16 + g;
        const int r1 = r0 + 8;
        eA0[i] = r0*16 + (c ^ swbits(r0));
        eA1[i] = r1*16 + (c ^ swbits(r1));
    }
    #pragma unroll
    for (int j = 0; j < 4; j++) {
        const int rn = wn*32 + j*8 + g;
        eB[j] = rn*16 + (c ^ swbits(rn));
    }

    int cur = 0;
    for (int k0 = 0; k0 < K; k0 += 32) {
        const bool has_next = (k0 + 32) < K;
        if (has_next) { loadA(k0 + 32); loadB(k0 + 32); }

        #pragma unroll
        for (int ks = 0; ks < 2; ks++) {
            const int kb = ks * 8;
            uint32_t af[4][4];
            #pragma unroll
            for (int i = 0; i < 4; i++) {
                af[i][0] = As[cur][eA0[i] ^ kb];
                af[i][1] = As[cur][eA1[i] ^ kb];
                af[i][2] = As[cur][eA0[i] ^ kb ^ 4];
                af[i][3] = As[cur][eA1[i] ^ kb ^ 4];
            }
            uint32_t bf[4][2];
            #pragma unroll
            for (int j = 0; j < 4; j++) {
                bf[j][0] = Bs[cur][eB[j] ^ kb];
                bf[j][1] = Bs[cur][eB[j] ^ kb ^ 4];
            }
            #pragma unroll
            for (int i = 0; i < 4; i++)
                #pragma unroll
                for (int j = 0; j < 4; j++) {
                    asm volatile(
                        "mma.sync.aligned.m16n8k16.row.col.f32.f16.f16.f32 "
                        "{%0,%1,%2,%3}, {%4,%5,%6,%7}, {%8,%9}, {%0,%1,%2,%3};\n"
                        : "+f"(acc[i][j][0]), "+f"(acc[i][j][1]),
                          "+f"(acc[i][j][2]), "+f"(acc[i][j][3])
                        : "r"(af[i][0]), "r"(af[i][1]), "r"(af[i][2]), "r"(af[i][3]),
                          "r"(bf[j][0]), "r"(bf[j][1]));
                }
        }

        if (has_next) { storeA(cur ^ 1); storeB(cur ^ 1); }
        __syncthreads();
        cur ^= 1;
    }

    // ---------------- epilogue ----------------
    const float gsc = (MODE == 3) ? gscale[0] : 0.f;
    const int tg = lane & 3;
    float*  Cf = reinterpret_cast<float*>(Cv);
    __half* Ch = reinterpret_cast<__half*>(Cv);

    #pragma unroll
    for (int i = 0; i < 4; i++) {
        const int rowB = m0 + wm*64 + i*16;
        #pragma unroll
        for (int j = 0; j < 4; j++) {
            const int colB = n0 + wn*32 + j*8 + tg*2;
            #pragma unroll
            for (int r = 0; r < 4; r++) {
                const int row = rowB + g + ((r >= 2) ? 8 : 0);
                const int col = colB + (r & 1);
                if (row >= M || col >= N) continue;
                float v = acc[i][j][r];
                if (MODE == 0) {
                    Cf[(long)blockIdx.z * cBS + (long)row * ldc + col] = v * alpha;
                } else if (MODE == 1) {
                    v = gelu_exact(v + bias[col]);
                    Ch[(long)blockIdx.z * cBS + (long)row * ldc + col] = __float2half_rn(v);
                } else if (MODE == 2) {
                    Ch[(long)blockIdx.z * cBS + (long)row * ldc + col] = __float2half_rn(v);
                } else {
                    v += bias[col];
                    const int b  = row / NTOK;
                    const int rr = row - b * NTOK;
                    const long off = ((long)b * NTOT + 1 + rr) * DIM + col;
                    Cf[off] = resid[off] + gsc * v;
                }
            }
        }
    }
}

// ---------------- pre-pass: x tokens -> half (compact) ----------------------
__global__ void convert_x_kernel(const float* __restrict__ img, __half* __restrict__ xh)
{
    const int t = blockIdx.x;
    const int b = t / NTOK, r = t - b*NTOK;
    const float2* src = reinterpret_cast<const float2*>(img + ((long)b*NTOT + 1 + r)*DIM);
    __half2* dst = reinterpret_cast<__half2*>(xh + (long)t*DIM);
    for (int j = threadIdx.x; j < DIM/2; j += blockDim.x)
        dst[j] = __float22half2_rn(src[j]);
}

// ---------------- pre-pass: x^T per batch, half, K-padded -------------------
__global__ void transpose_x_kernel(const float* __restrict__ img, __half* __restrict__ xT)
{
    __shared__ float tile[32][33];
    const int b  = blockIdx.z;
    const int t0 = blockIdx.x * 32;   // token tile (0..6 -> 224)
    const int d0 = blockIdx.y * 32;   // dim tile
    #pragma unroll
    for (int i = threadIdx.y; i < 32; i += 8) {
        const int t = t0 + i;
        float v = 0.f;
        if (t < NTOK) v = img[((long)b*NTOT + 1 + t)*DIM + d0 + threadIdx.x];
        tile[i][threadIdx.x] = v;
    }
    __syncthreads();
    #pragma unroll
    for (int i = threadIdx.y; i < 32; i += 8) {
        const int d = d0 + i;
        xT[((long)b*DIM + d)*KPAD + t0 + threadIdx.x] =
            __float2half_rn(tile[threadIdx.x][i]);
    }
}

// ---------------- pre-pass: weight transpose f32 -> half --------------------
__global__ void transpose_w_kernel(const float* __restrict__ w, __half* __restrict__ wT)
{
    __shared__ float tile[32][33];
    const int k0 = blockIdx.x * 32;
    const int n0 = blockIdx.y * 32;
    #pragma unroll
    for (int i = threadIdx.y; i < 32; i += 8)
        tile[i][threadIdx.x] = w[(long)(k0+i)*DIM + n0 + threadIdx.x];
    __syncthreads();
    #pragma unroll
    for (int i = threadIdx.y; i < 32; i += 8)
        wT[(long)(n0+i)*DIM + k0 + threadIdx.x] = __float2half_rn(tile[threadIdx.x][i]);
}

// ------- softmax rows of g_attn -> half g_attnh (stride KPAD, zero-pad) -----
__global__ void softmax_kernel(const float* __restrict__ S, __half* __restrict__ Sh)
{
    int warp = (blockIdx.x * blockDim.x + threadIdx.x) >> 5;
    int lane = threadIdx.x & 31;
    if (warp >= (int)(BQ * NTOK)) return;
    const float* p = S + (long)warp * NTOK;
    __half* ph = Sh + (long)warp * KPAD;

    float v[7], mx = -3.0e38f;
    #pragma unroll
    for (int it = 0; it < 7; it++) {
        int j = lane + it*32;
        v[it] = (j < NTOK) ? p[j] : -3.0e38f;
        mx = fmaxf(mx, v[it]);
    }
    #pragma unroll
    for (int o = 16; o; o >>= 1) mx = fmaxf(mx, __shfl_xor_sync(0xffffffffu, mx, o));
    float s = 0.f;
    #pragma unroll
    for (int it = 0; it < 7; it++) {
        int j = lane + it*32;
        if (j < NTOK) { v[it] = expf(v[it]-mx); s += v[it]; } else v[it] = 0.f;
    }
    #pragma unroll
    for (int o = 16; o; o >>= 1) s += __shfl_xor_sync(0xffffffffu, s, o);
    float inv = 1.f / s;
    #pragma unroll
    for (int it = 0; it < 7; it++) {
        int j = lane + it*32;   // covers exactly 0..223
        ph[j] = __float2half_rn((j < NTOK) ? v[it]*inv : 0.f);
    }
}

// ---------------- SIMT fp32 GEMM (tiny text-branch) --------------------------
template<int MODE>
__launch_bounds__(256)
__global__ void gemm_kernel(const float* __restrict__ A, int lda,
                            const float* __restrict__ B, int ldb,
                            float* __restrict__ C, int ldc,
                            int M, int N, int K,
                            const float* __restrict__ bias)
{
    const int BM = 64, BN = 64, BK = 16;
    __shared__ float Ast[BK][BM + 4];
    __shared__ float Bst[BK][BN];
    const int tid = threadIdx.x;
    const int tx = tid & 15, ty = tid >> 4;
    const int m0 = blockIdx.y * BM, n0 = blockIdx.x * BN;
    float acc[4][4] = {};
    const int aRow = tid >> 2, aCol = (tid & 3) * 4;

    for (int k0 = 0; k0 < K; k0 += BK) {
        {
            float4 v = make_float4(0.f,0.f,0.f,0.f);
            int gr = m0 + aRow;
            if (gr < M) {
                int gc = k0 + aCol;
                if (gc + 3 < K) v = *reinterpret_cast<const float4*>(A + (long)gr*lda + gc);
            }
            Ast[aCol+0][aRow]=v.x; Ast[aCol+1][aRow]=v.y;
            Ast[aCol+2][aRow]=v.z; Ast[aCol+3][aRow]=v.w;
        }
        {
            int br = tid >> 4, bc = (tid & 15) * 4;
            float4 v = make_float4(0.f,0.f,0.f,0.f);
            int gk = k0 + br, gn = n0 + bc;
            if (gk < K && gn + 3 < N)
                v = *reinterpret_cast<const float4*>(B + (long)gk*ldb + gn);
            *reinterpret_cast<float4*>(&Bst[br][bc]) = v;
        }
        __syncthreads();
        #pragma unroll
        for (int k = 0; k < BK; k++) {
            float4 av = *reinterpret_cast<const float4*>(&Ast[k][ty*4]);
            float4 bv = *reinterpret_cast<const float4*>(&Bst[k][tx*4]);
            acc[0][0]+=av.x*bv.x; acc[0][1]+=av.x*bv.y; acc[0][2]+=av.x*bv.z; acc[0][3]+=av.x*bv.w;
            acc[1][0]+=av.y*bv.x; acc[1][1]+=av.y*bv.y; acc[1][2]+=av.y*bv.z; acc[1][3]+=av.y*bv.w;
            acc[2][0]+=av.z*bv.x; acc[2][1]+=av.z*bv.y; acc[2][2]+=av.z*bv.z; acc[2][3]+=av.z*bv.w;
            acc[3][0]+=av.w*bv.x; acc[3][1]+=av.w*bv.y; acc[3][2]+=av.w*bv.z; acc[3][3]+=av.w*bv.w;
        }
        __syncthreads();
    }
    #pragma unroll
    for (int i = 0; i < 4; i++) {
        int m = m0 + ty*4 + i; if (m >= M) continue;
        #pragma unroll
        for (int j = 0; j < 4; j++) {
            int n = n0 + tx*4 + j; if (n >= N) continue;
            float v = acc[i][j] + bias[n];
            if (MODE == 1) v = gelu_exact(v);
            C[(long)m*ldc + n] = v;
        }
    }
}

__global__ void layernorm_kernel(float* __restrict__ X,
                                 const float* __restrict__ w,
                                 const float* __restrict__ b)
{
    int row = blockIdx.x;
    float* p = X + (long)row * DIM;
    float s = 0.f, sq = 0.f;
    for (int j = threadIdx.x; j < DIM; j += blockDim.x) {
        float x = p[j]; s += x; sq += x*x;
    }
    __shared__ float rs[32], rq[32];
    int lane = threadIdx.x & 31, wd = threadIdx.x >> 5;
    #pragma unroll
    for (int o = 16; o; o >>= 1) {
        s  += __shfl_xor_sync(0xffffffffu, s, o);
        sq += __shfl_xor_sync(0xffffffffu, sq, o);
    }
    if (lane == 0) { rs[wd] = s; rq[wd] = sq; }
    __syncthreads();
    int nw = blockDim.x >> 5;
    if (wd == 0) {
        float a = (lane < nw) ? rs[lane] : 0.f;
        float cc = (lane < nw) ? rq[lane] : 0.f;
        #pragma unroll
        for (int o = 16; o; o >>= 1) {
            a  += __shfl_xor_sync(0xffffffffu, a, o);
            cc += __shfl_xor_sync(0xffffffffu, cc, o);
        }
        if (lane == 0) { rs[0] = a; rq[0] = cc; }
    }
    __syncthreads();
    float mu = rs[0] / DIM;
    float var = rq[0] / DIM - mu*mu;
    float rstd = rsqrtf(var + 1e-5f);
    for (int j = threadIdx.x; j < DIM; j += blockDim.x)
        p[j] = (p[j]-mu)*rstd*w[j] + b[j];
}

__global__ void mask_refine_kernel(float* __restrict__ out,
                                   const float* __restrict__ tq,
                                   const float* __restrict__ gamma)
{
    int warp = (blockIdx.x * blockDim.x + threadIdx.x) >> 5;
    int lane = threadIdx.x & 31;
    if (warp >= (int)TTOT) return;
    int b = warp / NTOK, r = warp - b*NTOK;
    float* p = out + ((long)b*NTOT + 1 + r)*DIM;
    const float* t = tq + (long)b*DIM;
    float d = 0.f;
    for (int j = lane; j < DIM; j += 32) d += p[j]*t[j];
    #pragma unroll
    for (int o = 16; o; o >>= 1) d += __shfl_xor_sync(0xffffffffu, d, o);
    float sc = 1.f + gamma[0] / (1.f + expf(-d));
    for (int j = lane; j < DIM; j += 32) p[j] *= sc;
}

__global__ void copy_cls_kernel(const float* __restrict__ img, float* __restrict__ out)
{
    long base = (long)blockIdx.x * NTOT * DIM;
    for (int j = threadIdx.x; j < DIM; j += blockDim.x)
        out[base + j] = img[base + j];
}

// =====================================================================
extern "C" void kernel_launch(void* const* d_in, const int* in_sizes, int n_in,
                              void* d_out, int out_size)
{
    const float* img       = (const float*)d_in[0];
    const float* text      = (const float*)d_in[1];
    const float* w1_msg    = (const float*)d_in[2];
    const float* b1_msg    = (const float*)d_in[3];
    const float* w2_msg    = (const float*)d_in[4];
    const float* b2_msg    = (const float*)d_in[5];
    const float* gamma_gcn = (const float*)d_in[6];
    const float* w1_txt    = (const float*)d_in[7];
    const float* b1_txt    = (const float*)d_in[8];
    const float* w2_txt    = (const float*)d_in[9];
    const float* b2_txt    = (const float*)d_in[10];
    const float* ln_w      = (const float*)d_in[11];
    const float* ln_b      = (const float*)d_in[12];
    const float* gamma     = (const float*)d_in[13];
    float* out = (float*)d_out;

    float *attn, *txt, *tq;
    __half *attnh, *xh, *xT, *w1T, *w2T, *b1h, *b2h;
    cudaGetSymbolAddress((void**)&attn,  g_attn);
    cudaGetSymbolAddress((void**)&attnh, g_attnh);
    cudaGetSymbolAddress((void**)&xh,    g_xh);
    cudaGetSymbolAddress((void**)&xT,    g_xT);
    cudaGetSymbolAddress((void**)&w1T,   g_w1T);
    cudaGetSymbolAddress((void**)&w2T,   g_w2T);
    cudaGetSymbolAddress((void**)&b1h,   g_b1h);
    cudaGetSymbolAddress((void**)&b2h,   g_b2h);
    cudaGetSymbolAddress((void**)&txt,   g_txt);
    cudaGetSymbolAddress((void**)&tq,    g_tq);

    const float inv_sqrt_d = 0.03608439182435161f;  // 1/sqrt(768)

    // pre-passes (independent)
    copy_cls_kernel<<<BQ, 256>>>(img, out);
    convert_x_kernel<<<TTOT, 128>>>(img, xh);
    transpose_x_kernel<<<dim3(KPAD/32, DIM/32, BQ), dim3(32, 8)>>>(img, xT);
    transpose_w_kernel<<<dim3(DIM/32, DIM/32), dim3(32, 8)>>>(w1_msg, w1T);
    transpose_w_kernel<<<dim3(DIM/32, DIM/32), dim3(32, 8)>>>(w2_msg, w2T);

    // 1) scores: S[b] = xh xh^T / sqrt(D)  -> f32 attn
    hgemm_nt<0><<<dim3(2, 2, BQ), 256>>>(
        xh, (long)NTOK*DIM, DIM,
        xh, (long)NTOK*DIM, DIM,
        attn, (long)NTOK*NTOK, NTOK,
        NTOK, NTOK, DIM, inv_sqrt_d, nullptr, nullptr, nullptr);

    // 2) softmax -> half attnh (K-padded)
    softmax_kernel<<<(TTOT*32 + 255)/256, 256>>>(attn, attnh);

    // 3) msg = A @ x  ==  attnh (196xKPAD) * xT(768xKPAD)^T -> half b1h
    hgemm_nt<2><<<dim3(6, 2, BQ), 256>>>(
        attnh, (long)NTOK*KPAD, KPAD,
        xT, (long)DIM*KPAD, KPAD,
        b1h, (long)NTOK*DIM, DIM,
        NTOK, DIM, KPAD, 1.f, nullptr, nullptr, nullptr);

    // 4) h = gelu(msg @ w1 + b1) -> half b2h
    hgemm_nt<1><<<dim3(6, TTOT/128, 1), 256>>>(
        b1h, 0, DIM, w1T, 0, DIM, b2h, 0, DIM,
        TTOT, DIM, DIM, 1.f, b1_msg, nullptr, nullptr);

    // 5) x_new = x + gamma_gcn*(h @ w2 + b2) -> f32 d_out (remapped)
    hgemm_nt<3><<<dim3(6, TTOT/128, 1), 256>>>(
        b2h, 0, DIM, w2T, 0, DIM, out, 0, 0,
        TTOT, DIM, DIM, 1.f, b2_msg, img, gamma_gcn);

    // text branch (small, fp32 SIMT)
    gemm_kernel<1><<<dim3(12, 4, 1), 256>>>(
        text, DTXT, w1_txt, DIM, txt, DIM, BQ, DIM, DTXT, b1_txt);
    gemm_kernel<2><<<dim3(12, 4, 1), 256>>>(
        txt, DIM, w2_txt, DIM, tq, DIM, BQ, DIM, DIM, b2_txt);
    layernorm_kernel<<<BQ, 256>>>(tq, ln_w, ln_b);

    // gating epilogue in place on d_out token rows
    mask_refine_kernel<<<(TTOT*32 + 255)/256, 256>>>(out, tq, gamma);
}

// round 8
// speedup vs baseline: 1.9007x; 1.4145x over previous
#include <cuda_runtime.h>
#include <cuda_fp16.h>
#include <cstdint>

#define BQ   256
#define NTOK 196
#define NTOT 197
#define DIM  768
#define DTXT 512
#define TTOT (BQ*NTOK)
#define KPAD 224          // NTOK padded to multiple of 32

// ---------------- scratch (device globals) ----------------
__device__ float  g_attn [(size_t)BQ*NTOK*NTOK];   // f32 scores
__device__ __half g_attnh[(size_t)BQ*NTOK*KPAD];   // softmax(A), half, K-padded
__device__ __half g_xh  [(size_t)TTOT*DIM];        // x tokens, half
__device__ __half g_xT  [(size_t)BQ*DIM*KPAD];     // x^T per batch, half, padded
__device__ __half g_w1T [(size_t)DIM*DIM];
__device__ __half g_w2T [(size_t)DIM*DIM];
__device__ __half g_b1h [(size_t)TTOT*DIM];        // msg (half)
__device__ __half g_b2h [(size_t)TTOT*DIM];        // gelu(h) (half)
__device__ float  g_txt [(size_t)BQ*DIM];
__device__ float  g_tq  [(size_t)BQ*DIM];

__device__ __forceinline__ float gelu_exact(float x) { return x * normcdff(x); }

__device__ __forceinline__ void cp16(uint32_t dst, const void* src, bool ok) {
    int sz = ok ? 16 : 0;
    asm volatile("cp.async.cg.shared.global [%0], [%1], 16, %2;\n"
                 :: "r"(dst), "l"(src), "r"(sz));
}
#define CP_COMMIT() asm volatile("cp.async.commit_group;\n")
#define CP_WAIT1()  asm volatile("cp.async.wait_group 1;\n")

// =====================================================================
// fp16 NT GEMM (m16n8k16, fp32 accum): C = alpha * A(MxK) * B(NxK)^T
// A, B row-major half, K % 32 == 0, rows 16B-aligned. 128x128x32 tile,
// 8 warps, warp tile 64x32, 3-stage cp.async pipeline.
// Smem tile: [row][16 u32] with 16B-granular swizzle
//   group' = group ^ ((row>>1)&3)   (group = u32col>>2)
// -> cp.async 16B stores conflict-optimal, fragment LDS.32 reads
//    are exact 32-bank bijections.
// MODE 0: f32 C = alpha*acc
// MODE 1: half C = gelu(acc+bias)
// MODE 2: half C = acc
// MODE 3: f32 out[remap] = resid[remap] + g*(acc+bias)
// =====================================================================
template<int MODE>
__launch_bounds__(256, 2)
__global__ void hgemm_nt(const __half* __restrict__ A, long aBS, int lda,
                         const __half* __restrict__ B, long bBS, int ldb,
                         void* __restrict__ Cv, long cBS, int ldc,
                         int M, int N, int K, float alpha,
                         const float* __restrict__ bias,
                         const float* __restrict__ resid,
                         const float* __restrict__ gscale)
{
    __shared__ uint32_t As[3][128*16];   // 8KB per stage
    __shared__ uint32_t Bs[3][128*16];

    const int tid  = threadIdx.x;
    const int lane = tid & 31;
    const int wid  = tid >> 5;
    const int wm   = wid & 1;
    const int wn   = wid >> 1;
    const int m0   = blockIdx.y * 128;
    const int n0   = blockIdx.x * 128;

    const __half* Ab = A + (long)blockIdx.z * aBS;
    const __half* Bb = B + (long)blockIdx.z * bBS;

    const uint32_t asb = (uint32_t)__cvta_generic_to_shared(&As[0][0]);
    const uint32_t bsb = (uint32_t)__cvta_generic_to_shared(&Bs[0][0]);

    float acc[4][4][4];
    #pragma unroll
    for (int i = 0; i < 4; i++)
        #pragma unroll
        for (int j = 0; j < 4; j++)
            #pragma unroll
            for (int r = 0; r < 4; r++) acc[i][j][r] = 0.f;

    // loader geometry: thread covers row (tid>>1), 2x16B in half (tid&1) of row
    const int ld_r  = tid >> 1;
    const int ld_hs = tid & 1;
    const int ld_sw = (ld_r >> 1) & 3;                    // swizzle for this row
    const int gA    = ((ld_hs*2 + 0) ^ ld_sw) << 2;       // u32 col of 16B grp 0
    const int gB    = ((ld_hs*2 + 1) ^ ld_sw) << 2;       // u32 col of 16B grp 1
    const bool okA  = (m0 + ld_r) < M;
    const bool okB  = (n0 + ld_r) < N;
    const __half* pa = Ab + (long)(okA ? (m0 + ld_r) : 0) * lda + ld_hs*16;
    const __half* pb = Bb + (long)(okB ? (n0 + ld_r) : 0) * ldb + ld_hs*16;
    const uint32_t dA0 = asb + (uint32_t)(ld_r*16 + gA) * 4;
    const uint32_t dA1 = asb + (uint32_t)(ld_r*16 + gB) * 4;
    const uint32_t dB0 = bsb + (uint32_t)(ld_r*16 + gA) * 4;
    const uint32_t dB1 = bsb + (uint32_t)(ld_r*16 + gB) * 4;

    auto load_stage = [&](int st, int k0) {
        const uint32_t so = (uint32_t)(st * 2048 * 4);
        cp16(dA0 + so, pa + k0,     okA);
        cp16(dA1 + so, pa + k0 + 8, okA);
        cp16(dB0 + so, pb + k0,     okB);
        cp16(dB1 + so, pb + k0 + 8, okB);
    };

    const int NIT = K / 32;

    // prologue: stages 0,1 in flight
    load_stage(0, 0); CP_COMMIT();
    if (NIT > 1) load_stage(1, 32);
    CP_COMMIT();

    // fragment-read bases: idx = base + ((kb+dc) ^ sw)
    const int g = lane >> 2, c = lane & 3;
    int bA0[4], bA1[4], sA0[4], sA1[4], bB[4], sB[4];
    #pragma unroll
    for (int i = 0; i < 4; i++) {
        const int r0 = wm*64 + i*16 + g;
        const int r1 = r0 + 8;
        bA0[i] = r0*16 + c;  sA0[i] = ((r0 >> 1) & 3) << 2;
        bA1[i] = r1*16 + c;  sA1[i] = ((r1 >> 1) & 3) << 2;
    }
    #pragma unroll
    for (int j = 0; j < 4; j++) {
        const int rn = wn*32 + j*8 + g;
        bB[j] = rn*16 + c;   sB[j] = ((rn >> 1) & 3) << 2;
    }

    int cur = 0;
    for (int it = 0; it < NIT; it++) {
        CP_WAIT1();
        __syncthreads();
        if (it + 2 < NIT) load_stage((it + 2) % 3, (it + 2) * 32);
        CP_COMMIT();

        const uint32_t* Ac = &As[cur][0];
        const uint32_t* Bc = &Bs[cur][0];
        #pragma unroll
        for (int ks = 0; ks < 2; ks++) {
            const int kb = ks * 8;
            uint32_t af[4][4];
            #pragma unroll
            for (int i = 0; i < 4; i++) {
                af[i][0] = Ac[bA0[i] + (kb ^ sA0[i])];
                af[i][1] = Ac[bA1[i] + (kb ^ sA1[i])];
                af[i][2] = Ac[bA0[i] + ((kb + 4) ^ sA0[i])];
                af[i][3] = Ac[bA1[i] + ((kb + 4) ^ sA1[i])];
            }
            uint32_t bf[4][2];
            #pragma unroll
            for (int j = 0; j < 4; j++) {
                bf[j][0] = Bc[bB[j] + (kb ^ sB[j])];
                bf[j][1] = Bc[bB[j] + ((kb + 4) ^ sB[j])];
            }
            #pragma unroll
            for (int i = 0; i < 4; i++)
                #pragma unroll
                for (int j = 0; j < 4; j++) {
                    asm volatile(
                        "mma.sync.aligned.m16n8k16.row.col.f32.f16.f16.f32 "
                        "{%0,%1,%2,%3}, {%4,%5,%6,%7}, {%8,%9}, {%0,%1,%2,%3};\n"
                        : "+f"(acc[i][j][0]), "+f"(acc[i][j][1]),
                          "+f"(acc[i][j][2]), "+f"(acc[i][j][3])
                        : "r"(af[i][0]), "r"(af[i][1]), "r"(af[i][2]), "r"(af[i][3]),
                          "r"(bf[j][0]), "r"(bf[j][1]));
                }
        }
        cur = (cur + 1 == 3) ? 0 : cur + 1;
    }

    // ---------------- epilogue ----------------
    const float gsc = (MODE == 3) ? gscale[0] : 0.f;
    const int tg = lane & 3;
    float*  Cf = reinterpret_cast<float*>(Cv);
    __half* Ch = reinterpret_cast<__half*>(Cv);

    #pragma unroll
    for (int i = 0; i < 4; i++) {
        const int rowB = m0 + wm*64 + i*16;
        #pragma unroll
        for (int j = 0; j < 4; j++) {
            const int colB = n0 + wn*32 + j*8 + tg*2;
            #pragma unroll
            for (int r = 0; r < 4; r++) {
                const int row = rowB + g + ((r >= 2) ? 8 : 0);
                const int col = colB + (r & 1);
                if (row >= M || col >= N) continue;
                float v = acc[i][j][r];
                if (MODE == 0) {
                    Cf[(long)blockIdx.z * cBS + (long)row * ldc + col] = v * alpha;
                } else if (MODE == 1) {
                    v = gelu_exact(v + bias[col]);
                    Ch[(long)blockIdx.z * cBS + (long)row * ldc + col] = __float2half_rn(v);
                } else if (MODE == 2) {
                    Ch[(long)blockIdx.z * cBS + (long)row * ldc + col] = __float2half_rn(v);
                } else {
                    v += bias[col];
                    const int b  = row / NTOK;
                    const int rr = row - b * NTOK;
                    const long off = ((long)b * NTOT + 1 + rr) * DIM + col;
                    Cf[off] = resid[off] + gsc * v;
                }
            }
        }
    }
}

// ---------------- pre-pass: x tokens -> half (compact) ----------------------
__global__ void convert_x_kernel(const float* __restrict__ img, __half* __restrict__ xh)
{
    const int t = blockIdx.x;
    const int b = t / NTOK, r = t - b*NTOK;
    const float2* src = reinterpret_cast<const float2*>(img + ((long)b*NTOT + 1 + r)*DIM);
    __half2* dst = reinterpret_cast<__half2*>(xh + (long)t*DIM);
    for (int j = threadIdx.x; j < DIM/2; j += blockDim.x)
        dst[j] = __float22half2_rn(src[j]);
}

// ---------------- pre-pass: x^T per batch, half, K-padded -------------------
__global__ void transpose_x_kernel(const float* __restrict__ img, __half* __restrict__ xT)
{
    __shared__ float tile[32][33];
    const int b  = blockIdx.z;
    const int t0 = blockIdx.x * 32;
    const int d0 = blockIdx.y * 32;
    #pragma unroll
    for (int i = threadIdx.y; i < 32; i += 8) {
        const int t = t0 + i;
        float v = 0.f;
        if (t < NTOK) v = img[((long)b*NTOT + 1 + t)*DIM + d0 + threadIdx.x];
        tile[i][threadIdx.x] = v;
    }
    __syncthreads();
    #pragma unroll
    for (int i = threadIdx.y; i < 32; i += 8) {
        const int d = d0 + i;
        xT[((long)b*DIM + d)*KPAD + t0 + threadIdx.x] =
            __float2half_rn(tile[threadIdx.x][i]);
    }
}

// ---------------- pre-pass: weight transpose f32 -> half --------------------
__global__ void transpose_w_kernel(const float* __restrict__ w, __half* __restrict__ wT)
{
    __shared__ float tile[32][33];
    const int k0 = blockIdx.x * 32;
    const int n0 = blockIdx.y * 32;
    #pragma unroll
    for (int i = threadIdx.y; i < 32; i += 8)
        tile[i][threadIdx.x] = w[(long)(k0+i)*DIM + n0 + threadIdx.x];
    __syncthreads();
    #pragma unroll
    for (int i = threadIdx.y; i < 32; i += 8)
        wT[(long)(n0+i)*DIM + k0 + threadIdx.x] = __float2half_rn(tile[threadIdx.x][i]);
}

// ------- softmax rows of g_attn -> half g_attnh (stride KPAD, zero-pad) -----
__global__ void softmax_kernel(const float* __restrict__ S, __half* __restrict__ Sh)
{
    int warp = (blockIdx.x * blockDim.x + threadIdx.x) >> 5;
    int lane = threadIdx.x & 31;
    if (warp >= (int)(BQ * NTOK)) return;
    const float* p = S + (long)warp * NTOK;
    __half* ph = Sh + (long)warp * KPAD;

    float v[7], mx = -3.0e38f;
    #pragma unroll
    for (int it = 0; it < 7; it++) {
        int j = lane + it*32;
        v[it] = (j < NTOK) ? p[j] : -3.0e38f;
        mx = fmaxf(mx, v[it]);
    }
    #pragma unroll
    for (int o = 16; o; o >>= 1) mx = fmaxf(mx, __shfl_xor_sync(0xffffffffu, mx, o));
    float s = 0.f;
    #pragma unroll
    for (int it = 0; it < 7; it++) {
        int j = lane + it*32;
        if (j < NTOK) { v[it] = expf(v[it]-mx); s += v[it]; } else v[it] = 0.f;
    }
    #pragma unroll
    for (int o = 16; o; o >>= 1) s += __shfl_xor_sync(0xffffffffu, s, o);
    float inv = 1.f / s;
    #pragma unroll
    for (int it = 0; it < 7; it++) {
        int j = lane + it*32;
        ph[j] = __float2half_rn((j < NTOK) ? v[it]*inv : 0.f);
    }
}

// ---------------- SIMT fp32 GEMM (tiny text-branch) --------------------------
template<int MODE>
__launch_bounds__(256)
__global__ void gemm_kernel(const float* __restrict__ A, int lda,
                            const float* __restrict__ B, int ldb,
                            float* __restrict__ C, int ldc,
                            int M, int N, int K,
                            const float* __restrict__ bias)
{
    const int BM = 64, BN = 64, BK = 16;
    __shared__ float Ast[BK][BM + 4];
    __shared__ float Bst[BK][BN];
    const int tid = threadIdx.x;
    const int tx = tid & 15, ty = tid >> 4;
    const int m0 = blockIdx.y * BM, n0 = blockIdx.x * BN;
    float acc[4][4] = {};
    const int aRow = tid >> 2, aCol = (tid & 3) * 4;

    for (int k0 = 0; k0 < K; k0 += BK) {
        {
            float4 v = make_float4(0.f,0.f,0.f,0.f);
            int gr = m0 + aRow;
            if (gr < M) {
                int gc = k0 + aCol;
                if (gc + 3 < K) v = *reinterpret_cast<const float4*>(A + (long)gr*lda + gc);
            }
            Ast[aCol+0][aRow]=v.x; Ast[aCol+1][aRow]=v.y;
            Ast[aCol+2][aRow]=v.z; Ast[aCol+3][aRow]=v.w;
        }
        {
            int br = tid >> 4, bc = (tid & 15) * 4;
            float4 v = make_float4(0.f,0.f,0.f,0.f);
            int gk = k0 + br, gn = n0 + bc;
            if (gk < K && gn + 3 < N)
                v = *reinterpret_cast<const float4*>(B + (long)gk*ldb + gn);
            *reinterpret_cast<float4*>(&Bst[br][bc]) = v;
        }
        __syncthreads();
        #pragma unroll
        for (int k = 0; k < BK; k++) {
            float4 av = *reinterpret_cast<const float4*>(&Ast[k][ty*4]);
            float4 bv = *reinterpret_cast<const float4*>(&Bst[k][tx*4]);
            acc[0][0]+=av.x*bv.x; acc[0][1]+=av.x*bv.y; acc[0][2]+=av.x*bv.z; acc[0][3]+=av.x*bv.w;
            acc[1][0]+=av.y*bv.x; acc[1][1]+=av.y*bv.y; acc[1][2]+=av.y*bv.z; acc[1][3]+=av.y*bv.w;
            acc[2][0]+=av.z*bv.x; acc[2][1]+=av.z*bv.y; acc[2][2]+=av.z*bv.z; acc[2][3]+=av.z*bv.w;
            acc[3][0]+=av.w*bv.x; acc[3][1]+=av.w*bv.y; acc[3][2]+=av.w*bv.z; acc[3][3]+=av.w*bv.w;
        }
        __syncthreads();
    }
    #pragma unroll
    for (int i = 0; i < 4; i++) {
        int m = m0 + ty*4 + i; if (m >= M) continue;
        #pragma unroll
        for (int j = 0; j < 4; j++) {
            int n = n0 + tx*4 + j; if (n >= N) continue;
            float v = acc[i][j] + bias[n];
            if (MODE == 1) v = gelu_exact(v);
            C[(long)m*ldc + n] = v;
        }
    }
}

__global__ void layernorm_kernel(float* __restrict__ X,
                                 const float* __restrict__ w,
                                 const float* __restrict__ b)
{
    int row = blockIdx.x;
    float* p = X + (long)row * DIM;
    float s = 0.f, sq = 0.f;
    for (int j = threadIdx.x; j < DIM; j += blockDim.x) {
        float x = p[j]; s += x; sq += x*x;
    }
    __shared__ float rs[32], rq[32];
    int lane = threadIdx.x & 31, wd = threadIdx.x >> 5;
    #pragma unroll
    for (int o = 16; o; o >>= 1) {
        s  += __shfl_xor_sync(0xffffffffu, s, o);
        sq += __shfl_xor_sync(0xffffffffu, sq, o);
    }
    if (lane == 0) { rs[wd] = s; rq[wd] = sq; }
    __syncthreads();
    int nw = blockDim.x >> 5;
    if (wd == 0) {
        float a = (lane < nw) ? rs[lane] : 0.f;
        float cc = (lane < nw) ? rq[lane] : 0.f;
        #pragma unroll
        for (int o = 16; o; o >>= 1) {
            a  += __shfl_xor_sync(0xffffffffu, a, o);
            cc += __shfl_xor_sync(0xffffffffu, cc, o);
        }
        if (lane == 0) { rs[0] = a; rq[0] = cc; }
    }
    __syncthreads();
    float mu = rs[0] / DIM;
    float var = rq[0] / DIM - mu*mu;
    float rstd = rsqrtf(var + 1e-5f);
    for (int j = threadIdx.x; j < DIM; j += blockDim.x)
        p[j] = (p[j]-mu)*rstd*w[j] + b[j];
}

__global__ void mask_refine_kernel(float* __restrict__ out,
                                   const float* __restrict__ tq,
                                   const float* __restrict__ gamma)
{
    int warp = (blockIdx.x * blockDim.x + threadIdx.x) >> 5;
    int lane = threadIdx.x & 31;
    if (warp >= (int)TTOT) return;
    int b = warp / NTOK, r = warp - b*NTOK;
    float* p = out + ((long)b*NTOT + 1 + r)*DIM;
    const float* t = tq + (long)b*DIM;
    float d = 0.f;
    for (int j = lane; j < DIM; j += 32) d += p[j]*t[j];
    #pragma unroll
    for (int o = 16; o; o >>= 1) d += __shfl_xor_sync(0xffffffffu, d, o);
    float sc = 1.f + gamma[0] / (1.f + expf(-d));
    for (int j = lane; j < DIM; j += 32) p[j] *= sc;
}

__global__ void copy_cls_kernel(const float* __restrict__ img, float* __restrict__ out)
{
    long base = (long)blockIdx.x * NTOT * DIM;
    for (int j = threadIdx.x; j < DIM; j += blockDim.x)
        out[base + j] = img[base + j];
}

// =====================================================================
extern "C" void kernel_launch(void* const* d_in, const int* in_sizes, int n_in,
                              void* d_out, int out_size)
{
    const float* img       = (const float*)d_in[0];
    const float* text      = (const float*)d_in[1];
    const float* w1_msg    = (const float*)d_in[2];
    const float* b1_msg    = (const float*)d_in[3];
    const float* w2_msg    = (const float*)d_in[4];
    const float* b2_msg    = (const float*)d_in[5];
    const float* gamma_gcn = (const float*)d_in[6];
    const float* w1_txt    = (const float*)d_in[7];
    const float* b1_txt    = (const float*)d_in[8];
    const float* w2_txt    = (const float*)d_in[9];
    const float* b2_txt    = (const float*)d_in[10];
    const float* ln_w      = (const float*)d_in[11];
    const float* ln_b      = (const float*)d_in[12];
    const float* gamma     = (const float*)d_in[13];
    float* out = (float*)d_out;

    float *attn, *txt, *tq;
    __half *attnh, *xh, *xT, *w1T, *w2T, *b1h, *b2h;
    cudaGetSymbolAddress((void**)&attn,  g_attn);
    cudaGetSymbolAddress((void**)&attnh, g_attnh);
    cudaGetSymbolAddress((void**)&xh,    g_xh);
    cudaGetSymbolAddress((void**)&xT,    g_xT);
    cudaGetSymbolAddress((void**)&w1T,   g_w1T);
    cudaGetSymbolAddress((void**)&w2T,   g_w2T);
    cudaGetSymbolAddress((void**)&b1h,   g_b1h);
    cudaGetSymbolAddress((void**)&b2h,   g_b2h);
    cudaGetSymbolAddress((void**)&txt,   g_txt);
    cudaGetSymbolAddress((void**)&tq,    g_tq);

    const float inv_sqrt_d = 0.03608439182435161f;  // 1/sqrt(768)

    // pre-passes (independent)
    copy_cls_kernel<<<BQ, 256>>>(img, out);
    convert_x_kernel<<<TTOT, 128>>>(img, xh);
    transpose_x_kernel<<<dim3(KPAD/32, DIM/32, BQ), dim3(32, 8)>>>(img, xT);
    transpose_w_kernel<<<dim3(DIM/32, DIM/32), dim3(32, 8)>>>(w1_msg, w1T);
    transpose_w_kernel<<<dim3(DIM/32, DIM/32), dim3(32, 8)>>>(w2_msg, w2T);

    // 1) scores: S[b] = xh xh^T / sqrt(D)  -> f32 attn
    hgemm_nt<0><<<dim3(2, 2, BQ), 256>>>(
        xh, (long)NTOK*DIM, DIM,
        xh, (long)NTOK*DIM, DIM,
        attn, (long)NTOK*NTOK, NTOK,
        NTOK, NTOK, DIM, inv_sqrt_d, nullptr, nullptr, nullptr);

    // 2) softmax -> half attnh (K-padded)
    softmax_kernel<<<(TTOT*32 + 255)/256, 256>>>(attn, attnh);

    // 3) msg = A @ x  ==  attnh (196xKPAD) * xT(768xKPAD)^T -> half b1h
    hgemm_nt<2><<<dim3(6, 2, BQ), 256>>>(
        attnh, (long)NTOK*KPAD, KPAD,
        xT, (long)DIM*KPAD, KPAD,
        b1h, (long)NTOK*DIM, DIM,
        NTOK, DIM, KPAD, 1.f, nullptr, nullptr, nullptr);

    // 4) h = gelu(msg @ w1 + b1) -> half b2h
    hgemm_nt<1><<<dim3(6, TTOT/128, 1), 256>>>(
        b1h, 0, DIM, w1T, 0, DIM, b2h, 0, DIM,
        TTOT, DIM, DIM, 1.f, b1_msg, nullptr, nullptr);

    // 5) x_new = x + gamma_gcn*(h @ w2 + b2) -> f32 d_out (remapped)
    hgemm_nt<3><<<dim3(6, TTOT/128, 1), 256>>>(
        b2h, 0, DIM, w2T, 0, DIM, out, 0, 0,
        TTOT, DIM, DIM, 1.f, b2_msg, img, gamma_gcn);

    // text branch (small, fp32 SIMT)
    gemm_kernel<1><<<dim3(12, 4, 1), 256>>>(
        text, DTXT, w1_txt, DIM, txt, DIM, BQ, DIM, DTXT, b1_txt);
    gemm_kernel<2><<<dim3(12, 4, 1), 256>>>(
        txt, DIM, w2_txt, DIM, tq, DIM, BQ, DIM, DIM, b2_txt);
    layernorm_kernel<<<BQ, 256>>>(tq, ln_w, ln_b);

    // gating epilogue in place on d_out token rows
    mask_refine_kernel<<<(TTOT*32 + 255)/256, 256>>>(out, tq, gamma);
}

// round 10
// speedup vs baseline: 2.2855x; 1.2024x over previous
#include <cuda_runtime.h>
#include <cuda_fp16.h>
#include <cstdint>

#define BQ   256
#define NTOK 196
#define NTOT 197
#define DIM  768
#define DTXT 512
#define TTOT (BQ*NTOK)
#define KPAD 224

// ---------------- scratch (device globals) ----------------
__device__ float  g_attn [(size_t)BQ*NTOK*NTOK];
__device__ __half g_attnh[(size_t)BQ*NTOK*KPAD];
__device__ __half g_xh  [(size_t)TTOT*DIM];
__device__ __half g_xT  [(size_t)BQ*DIM*KPAD];
__device__ __half g_w1T [(size_t)DIM*DIM];
__device__ __half g_w2T [(size_t)DIM*DIM];
__device__ __half g_b1h [(size_t)TTOT*DIM];
__device__ __half g_b2h [(size_t)TTOT*DIM];
__device__ float  g_txt [(size_t)BQ*DIM];
__device__ float  g_tq  [(size_t)BQ*DIM];
__device__ float  g_dot [(size_t)TTOT];

__device__ __forceinline__ float gelu_exact(float x) { return x * normcdff(x); }

__device__ __forceinline__ void cp16(uint32_t dst, const void* src, bool ok) {
    int sz = ok ? 16 : 0;
    asm volatile("cp.async.cg.shared.global [%0], [%1], 16, %2;\n"
                 :: "r"(dst), "l"(src), "r"(sz));
}
#define CP_COMMIT() asm volatile("cp.async.commit_group;\n")
#define CP_WAIT1()  asm volatile("cp.async.wait_group 1;\n")

// =====================================================================
// fp16 NT GEMM via mma.sync (R8-proven core): C = alpha*A(MxK)*B(NxK)^T
// A,B row-major half, K%32==0, rows 16B aligned. 128x128x32 tile,
// 8 warps (warp 64x32), 3-stage cp.async pipeline, swizzled smem.
// MODE 0: f32 C = alpha*acc                       (scores; M,N guards)
// MODE 2: half C = acc                            (msg; M guard)
// MODE 1: half C = gelu(acc+bias)                 (mlp1; exact tiles)
// MODE 3: f32 out[remap]=resid[remap]+g*(acc+bias) + dot accum (mlp2)
// =====================================================================
template<int MODE>
__launch_bounds__(256, 2)
__global__ void hgemm_nt(const __half* __restrict__ A, long aBS, int lda,
                         const __half* __restrict__ B, long bBS, int ldb,
                         void* __restrict__ Cv, long cBS, int ldc,
                         int M, int N, int K, float alpha,
                         const float* __restrict__ bias,
                         const float* __restrict__ resid,
                         const float* __restrict__ gscale,
                         const float* __restrict__ tq,
                         float* __restrict__ dotp)
{
    __shared__ uint32_t As[3][128*16];
    __shared__ uint32_t Bs[3][128*16];

    const int tid  = threadIdx.x;
    const int lane = tid & 31;
    const int wid  = tid >> 5;
    const int wm   = wid & 1;
    const int wn   = wid >> 1;
    const int m0   = blockIdx.y * 128;
    const int n0   = blockIdx.x * 128;

    const __half* Ab = A + (long)blockIdx.z * aBS;
    const __half* Bb = B + (long)blockIdx.z * bBS;

    const uint32_t asb = (uint32_t)__cvta_generic_to_shared(&As[0][0]);
    const uint32_t bsb = (uint32_t)__cvta_generic_to_shared(&Bs[0][0]);

    float acc[4][4][4];
    #pragma unroll
    for (int i = 0; i < 4; i++)
        #pragma unroll
        for (int j = 0; j < 4; j++)
            #pragma unroll
            for (int r = 0; r < 4; r++) acc[i][j][r] = 0.f;

    const int ld_r  = tid >> 1;
    const int ld_hs = tid & 1;
    const int ld_sw = (ld_r >> 1) & 3;
    const int gA    = ((ld_hs*2 + 0) ^ ld_sw) << 2;
    const int gB    = ((ld_hs*2 + 1) ^ ld_sw) << 2;
    const bool okA  = (m0 + ld_r) < M;
    const bool okB  = (n0 + ld_r) < N;
    const __half* pa = Ab + (long)(okA ? (m0 + ld_r) : 0) * lda + ld_hs*16;
    const __half* pb = Bb + (long)(okB ? (n0 + ld_r) : 0) * ldb + ld_hs*16;
    const uint32_t dA0 = asb + (uint32_t)(ld_r*16 + gA) * 4;
    const uint32_t dA1 = asb + (uint32_t)(ld_r*16 + gB) * 4;
    const uint32_t dB0 = bsb + (uint32_t)(ld_r*16 + gA) * 4;
    const uint32_t dB1 = bsb + (uint32_t)(ld_r*16 + gB) * 4;

    auto load_stage = [&](int st, int k0) {
        const uint32_t so = (uint32_t)(st * 2048 * 4);
        cp16(dA0 + so, pa + k0,     okA);
        cp16(dA1 + so, pa + k0 + 8, okA);
        cp16(dB0 + so, pb + k0,     okB);
        cp16(dB1 + so, pb + k0 + 8, okB);
    };

    const int NIT = K / 32;
    load_stage(0, 0); CP_COMMIT();
    if (NIT > 1) load_stage(1, 32);
    CP_COMMIT();

    const int g = lane >> 2, c = lane & 3;
    int bA0[4], bA1[4], sA0[4], sA1[4], bB[4], sB[4];
    #pragma unroll
    for (int i = 0; i < 4; i++) {
        const int r0 = wm*64 + i*16 + g;
        const int r1 = r0 + 8;
        bA0[i] = r0*16 + c;  sA0[i] = ((r0 >> 1) & 3) << 2;
        bA1[i] = r1*16 + c;  sA1[i] = ((r1 >> 1) & 3) << 2;
    }
    #pragma unroll
    for (int j = 0; j < 4; j++) {
        const int rn = wn*32 + j*8 + g;
        bB[j] = rn*16 + c;   sB[j] = ((rn >> 1) & 3) << 2;
    }

    int cur = 0;
    for (int it = 0; it < NIT; it++) {
        CP_WAIT1();
        __syncthreads();
        if (it + 2 < NIT) load_stage((it + 2) % 3, (it + 2) * 32);
        CP_COMMIT();

        const uint32_t* Ac = &As[cur][0];
        const uint32_t* Bc = &Bs[cur][0];
        #pragma unroll
        for (int ks = 0; ks < 2; ks++) {
            const int kb = ks * 8;
            uint32_t af[4][4];
            #pragma unroll
            for (int i = 0; i < 4; i++) {
                af[i][0] = Ac[bA0[i] + (kb ^ sA0[i])];
                af[i][1] = Ac[bA1[i] + (kb ^ sA1[i])];
                af[i][2] = Ac[bA0[i] + ((kb + 4) ^ sA0[i])];
                af[i][3] = Ac[bA1[i] + ((kb + 4) ^ sA1[i])];
            }
            uint32_t bf[4][2];
            #pragma unroll
            for (int j = 0; j < 4; j++) {
                bf[j][0] = Bc[bB[j] + (kb ^ sB[j])];
                bf[j][1] = Bc[bB[j] + ((kb + 4) ^ sB[j])];
            }
            #pragma unroll
            for (int i = 0; i < 4; i++)
                #pragma unroll
                for (int j = 0; j < 4; j++) {
                    asm volatile(
                        "mma.sync.aligned.m16n8k16.row.col.f32.f16.f16.f32 "
                        "{%0,%1,%2,%3}, {%4,%5,%6,%7}, {%8,%9}, {%0,%1,%2,%3};\n"
                        : "+f"(acc[i][j][0]), "+f"(acc[i][j][1]),
                          "+f"(acc[i][j][2]), "+f"(acc[i][j][3])
                        : "r"(af[i][0]), "r"(af[i][1]), "r"(af[i][2]), "r"(af[i][3]),
                          "r"(bf[j][0]), "r"(bf[j][1]));
                }
        }
        cur = (cur + 1 == 3) ? 0 : cur + 1;
    }

    // ---------------- epilogue (per MODE; col pairs are contiguous) ----------
    const int tg = lane & 3;

    if (MODE == 0) {            // scores: f32 = alpha*acc, M/N guards
        float* Cf = reinterpret_cast<float*>(Cv) + (long)blockIdx.z * cBS;
        #pragma unroll
        for (int i = 0; i < 4; i++)
            #pragma unroll
            for (int hi = 0; hi < 2; hi++) {
                const int row = m0 + wm*64 + i*16 + g + 8*hi;
                if (row >= M) continue;
                #pragma unroll
                for (int j = 0; j < 4; j++) {
                    const int col = n0 + wn*32 + j*8 + tg*2;
                    if (col >= N) continue;   // N even -> col+1 < N too
                    float2 o = make_float2(acc[i][j][2*hi+0] * alpha,
                                           acc[i][j][2*hi+1] * alpha);
                    *reinterpret_cast<float2*>(Cf + (long)row*ldc + col) = o;
                }
            }
    } else if (MODE == 2) {     // msg: half = acc, M guard only (N=768 exact)
        __half* Ch = reinterpret_cast<__half*>(Cv) + (long)blockIdx.z * cBS;
        #pragma unroll
        for (int i = 0; i < 4; i++)
            #pragma unroll
            for (int hi = 0; hi < 2; hi++) {
                const int row = m0 + wm*64 + i*16 + g + 8*hi;
                if (row >= M) continue;
                #pragma unroll
                for (int j = 0; j < 4; j++) {
                    const int col = n0 + wn*32 + j*8 + tg*2;
                    *reinterpret_cast<__half2*>(Ch + (long)row*ldc + col) =
                        __floats2half2_rn(acc[i][j][2*hi+0], acc[i][j][2*hi+1]);
                }
            }
    } else if (MODE == 1) {     // mlp1: half = gelu(acc+bias), exact tiles
        __half* Ch = reinterpret_cast<__half*>(Cv);
        #pragma unroll
        for (int i = 0; i < 4; i++)
            #pragma unroll
            for (int hi = 0; hi < 2; hi++) {
                const int row = m0 + wm*64 + i*16 + g + 8*hi;
                #pragma unroll
                for (int j = 0; j < 4; j++) {
                    const int col = n0 + wn*32 + j*8 + tg*2;
                    float v0 = gelu_exact(acc[i][j][2*hi+0] + bias[col]);
                    float v1 = gelu_exact(acc[i][j][2*hi+1] + bias[col+1]);
                    *reinterpret_cast<__half2*>(Ch + (long)row*ldc + col) =
                        __floats2half2_rn(v0, v1);
                }
            }
    } else {                    // mlp2: residual+remap + dot accumulation
        float* Cf = reinterpret_cast<float*>(Cv);
        const float gsc = gscale[0];
        #pragma unroll
        for (int i = 0; i < 4; i++)
            #pragma unroll
            for (int hi = 0; hi < 2; hi++) {
                const int row = m0 + wm*64 + i*16 + g + 8*hi;   // token index
                const int b   = row / NTOK;
                const int rr  = row - b * NTOK;
                const long off = ((long)b * NTOT + 1 + rr) * DIM;
                const float* tqr = tq + (long)b * DIM;
                float part = 0.f;
                #pragma unroll
                for (int j = 0; j < 4; j++) {
                    const int col = n0 + wn*32 + j*8 + tg*2;
                    float2 rv = *reinterpret_cast<const float2*>(resid + off + col);
                    float2 tv = *reinterpret_cast<const float2*>(tqr + col);
                    float o0 = rv.x + gsc * (acc[i][j][2*hi+0] + bias[col]);
                    float o1 = rv.y + gsc * (acc[i][j][2*hi+1] + bias[col+1]);
                    *reinterpret_cast<float2*>(Cf + off + col) = make_float2(o0, o1);
                    part += o0 * tv.x + o1 * tv.y;
                }
                atomicAdd(dotp + row, part);
            }
    }
}

// ------- fused pre-pass: img tokens -> xh (row-major half) + xT (half^T) -----
__global__ void prep_x_kernel(const float* __restrict__ img,
                              __half* __restrict__ xh, __half* __restrict__ xT)
{
    __shared__ float tile[32][33];
    const int b  = blockIdx.z;
    const int t0 = blockIdx.x * 32;   // token tile (KPAD/32 = 7)
    const int d0 = blockIdx.y * 32;
    #pragma unroll
    for (int i = threadIdx.y; i < 32; i += 8) {
        const int t = t0 + i;
        float v = 0.f;
        if (t < NTOK) {
            v = img[((long)b*NTOT + 1 + t)*DIM + d0 + threadIdx.x];
            xh[((long)b*NTOK + t)*DIM + d0 + threadIdx.x] = __float2half_rn(v);
        }
        tile[i][threadIdx.x] = v;
    }
    __syncthreads();
    #pragma unroll
    for (int i = threadIdx.y; i < 32; i += 8) {
        const int d = d0 + i;
        xT[((long)b*DIM + d)*KPAD + t0 + threadIdx.x] =
            __float2half_rn(tile[threadIdx.x][i]);
    }
}

// ---------------- pre-pass: weight transpose f32 -> half --------------------
__global__ void transpose_w_kernel(const float* __restrict__ w, __half* __restrict__ wT)
{
    __shared__ float tile[32][33];
    const int k0 = blockIdx.x * 32;
    const int n0 = blockIdx.y * 32;
    #pragma unroll
    for (int i = threadIdx.y; i < 32; i += 8)
        tile[i][threadIdx.x] = w[(long)(k0+i)*DIM + n0 + threadIdx.x];
    __syncthreads();
    #pragma unroll
    for (int i = threadIdx.y; i < 32; i += 8)
        wT[(long)(n0+i)*DIM + k0 + threadIdx.x] = __float2half_rn(tile[threadIdx.x][i]);
}

// ------- softmax rows of g_attn -> half g_attnh (stride KPAD, zero-pad) -----
__global__ void softmax_kernel(const float* __restrict__ S, __half* __restrict__ Sh)
{
    int warp = (blockIdx.x * blockDim.x + threadIdx.x) >> 5;
    int lane = threadIdx.x & 31;
    if (warp >= (int)(BQ * NTOK)) return;
    const float* p = S + (long)warp * NTOK;
    __half* ph = Sh + (long)warp * KPAD;

    float v[7], mx = -3.0e38f;
    #pragma unroll
    for (int it = 0; it < 7; it++) {
        int j = lane + it*32;
        v[it] = (j < NTOK) ? p[j] : -3.0e38f;
        mx = fmaxf(mx, v[it]);
    }
    #pragma unroll
    for (int o = 16; o; o >>= 1) mx = fmaxf(mx, __shfl_xor_sync(0xffffffffu, mx, o));
    float s = 0.f;
    #pragma unroll
    for (int it = 0; it < 7; it++) {
        int j = lane + it*32;
        if (j < NTOK) { v[it] = expf(v[it]-mx); s += v[it]; } else v[it] = 0.f;
    }
    #pragma unroll
    for (int o = 16; o; o >>= 1) s += __shfl_xor_sync(0xffffffffu, s, o);
    float inv = 1.f / s;
    #pragma unroll
    for (int it = 0; it < 7; it++) {
        int j = lane + it*32;
        ph[j] = __float2half_rn((j < NTOK) ? v[it]*inv : 0.f);
    }
}

// ---------------- SIMT fp32 GEMM (tiny text-branch) --------------------------
template<int MODE>
__launch_bounds__(256)
__global__ void gemm_kernel(const float* __restrict__ A, int lda,
                            const float* __restrict__ B, int ldb,
                            float* __restrict__ C, int ldc,
                            int M, int N, int K,
                            const float* __restrict__ bias)
{
    const int BM = 64, BN = 64, BK = 16;
    __shared__ float Ast[BK][BM + 4];
    __shared__ float Bst[BK][BN];
    const int tid = threadIdx.x;
    const int tx = tid & 15, ty = tid >> 4;
    const int m0 = blockIdx.y * BM, n0 = blockIdx.x * BN;
    float acc[4][4] = {};
    const int aRow = tid >> 2, aCol = (tid & 3) * 4;

    for (int k0 = 0; k0 < K; k0 += BK) {
        {
            float4 v = make_float4(0.f,0.f,0.f,0.f);
            int gr = m0 + aRow;
            if (gr < M) {
                int gc = k0 + aCol;
                if (gc + 3 < K) v = *reinterpret_cast<const float4*>(A + (long)gr*lda + gc);
            }
            Ast[aCol+0][aRow]=v.x; Ast[aCol+1][aRow]=v.y;
            Ast[aCol+2][aRow]=v.z; Ast[aCol+3][aRow]=v.w;
        }
        {
            int br = tid >> 4, bc = (tid & 15) * 4;
            float4 v = make_float4(0.f,0.f,0.f,0.f);
            int gk = k0 + br, gn = n0 + bc;
            if (gk < K && gn + 3 < N)
                v = *reinterpret_cast<const float4*>(B + (long)gk*ldb + gn);
            *reinterpret_cast<float4*>(&Bst[br][bc]) = v;
        }
        __syncthreads();
        #pragma unroll
        for (int k = 0; k < BK; k++) {
            float4 av = *reinterpret_cast<const float4*>(&Ast[k][ty*4]);
            float4 bv = *reinterpret_cast<const float4*>(&Bst[k][tx*4]);
            acc[0][0]+=av.x*bv.x; acc[0][1]+=av.x*bv.y; acc[0][2]+=av.x*bv.z; acc[0][3]+=av.x*bv.w;
            acc[1][0]+=av.y*bv.x; acc[1][1]+=av.y*bv.y; acc[1][2]+=av.y*bv.z; acc[1][3]+=av.y*bv.w;
            acc[2][0]+=av.z*bv.x; acc[2][1]+=av.z*bv.y; acc[2][2]+=av.z*bv.z; acc[2][3]+=av.z*bv.w;
            acc[3][0]+=av.w*bv.x; acc[3][1]+=av.w*bv.y; acc[3][2]+=av.w*bv.z; acc[3][3]+=av.w*bv.w;
        }
        __syncthreads();
    }
    #pragma unroll
    for (int i = 0; i < 4; i++) {
        int m = m0 + ty*4 + i; if (m >= M) continue;
        #pragma unroll
        for (int j = 0; j < 4; j++) {
            int n = n0 + tx*4 + j; if (n >= N) continue;
            float v = acc[i][j] + bias[n];
            if (MODE == 1) v = gelu_exact(v);
            C[(long)m*ldc + n] = v;
        }
    }
}

__global__ void layernorm_kernel(float* __restrict__ X,
                                 const float* __restrict__ w,
                                 const float* __restrict__ b)
{
    int row = blockIdx.x;
    float* p = X + (long)row * DIM;
    float s = 0.f, sq = 0.f;
    for (int j = threadIdx.x; j < DIM; j += blockDim.x) {
        float x = p[j]; s += x; sq += x*x;
    }
    __shared__ float rs[32], rq[32];
    int lane = threadIdx.x & 31, wd = threadIdx.x >> 5;
    #pragma unroll
    for (int o = 16; o; o >>= 1) {
        s  += __shfl_xor_sync(0xffffffffu, s, o);
        sq += __shfl_xor_sync(0xffffffffu, sq, o);
    }
    if (lane == 0) { rs[wd] = s; rq[wd] = sq; }
    __syncthreads();
    int nw = blockDim.x >> 5;
    if (wd == 0) {
        float a = (lane < nw) ? rs[lane] : 0.f;
        float cc = (lane < nw) ? rq[lane] : 0.f;
        #pragma unroll
        for (int o = 16; o; o >>= 1) {
            a  += __shfl_xor_sync(0xffffffffu, a, o);
            cc += __shfl_xor_sync(0xffffffffu, cc, o);
        }
        if (lane == 0) { rs[0] = a; rq[0] = cc; }
    }
    __syncthreads();
    float mu = rs[0] / DIM;
    float var = rq[0] / DIM - mu*mu;
    float rstd = rsqrtf(var + 1e-5f);
    for (int j = threadIdx.x; j < DIM; j += blockDim.x)
        p[j] = (p[j]-mu)*rstd*w[j] + b[j];
}

// ----- gating scale pass: out_row *= (1 + gamma*sigmoid(dot[row])) -----------
__global__ void mask_scale_kernel(float* __restrict__ out,
                                  const float* __restrict__ dotp,
                                  const float* __restrict__ gamma)
{
    const int t = blockIdx.x;                 // token index 0..TTOT-1
    const int b = t / NTOK, r = t - b*NTOK;
    const float sc = 1.f + gamma[0] / (1.f + expf(-dotp[t]));
    float4* p = reinterpret_cast<float4*>(out + ((long)b*NTOT + 1 + r)*DIM);
    const int j = threadIdx.x;                // blockDim = 192 = DIM/4
    float4 v = p[j];
    v.x *= sc; v.y *= sc; v.z *= sc; v.w *= sc;
    p[j] = v;
}

__global__ void copy_cls_kernel(const float* __restrict__ img, float* __restrict__ out)
{
    long base = (long)blockIdx.x * NTOT * DIM;
    for (int j = threadIdx.x; j < DIM; j += blockDim.x)
        out[base + j] = img[base + j];
}

// =====================================================================
extern "C" void kernel_launch(void* const* d_in, const int* in_sizes, int n_in,
                              void* d_out, int out_size)
{
    const float* img       = (const float*)d_in[0];
    const float* text      = (const float*)d_in[1];
    const float* w1_msg    = (const float*)d_in[2];
    const float* b1_msg    = (const float*)d_in[3];
    const float* w2_msg    = (const float*)d_in[4];
    const float* b2_msg    = (const float*)d_in[5];
    const float* gamma_gcn = (const float*)d_in[6];
    const float* w1_txt    = (const float*)d_in[7];
    const float* b1_txt    = (const float*)d_in[8];
    const float* w2_txt    = (const float*)d_in[9];
    const float* b2_txt    = (const float*)d_in[10];
    const float* ln_w      = (const float*)d_in[11];
    const float* ln_b      = (const float*)d_in[12];
    const float* gamma     = (const float*)d_in[13];
    float* out = (float*)d_out;

    float *attn, *txt, *tq, *dotp;
    __half *attnh, *xh, *xT, *w1T, *w2T, *b1h, *b2h;
    cudaGetSymbolAddress((void**)&attn,  g_attn);
    cudaGetSymbolAddress((void**)&attnh, g_attnh);
    cudaGetSymbolAddress((void**)&xh,    g_xh);
    cudaGetSymbolAddress((void**)&xT,    g_xT);
    cudaGetSymbolAddress((void**)&w1T,   g_w1T);
    cudaGetSymbolAddress((void**)&w2T,   g_w2T);
    cudaGetSymbolAddress((void**)&b1h,   g_b1h);
    cudaGetSymbolAddress((void**)&b2h,   g_b2h);
    cudaGetSymbolAddress((void**)&txt,   g_txt);
    cudaGetSymbolAddress((void**)&tq,    g_tq);
    cudaGetSymbolAddress((void**)&dotp,  g_dot);

    const float inv_sqrt_d = 0.03608439182435161f;  // 1/sqrt(768)

    // zero the dot accumulator (graph-capturable async memset)
    cudaMemsetAsync(dotp, 0, (size_t)TTOT * sizeof(float));

    // pre-passes (independent)
    copy_cls_kernel<<<BQ, 256>>>(img, out);
    prep_x_kernel<<<dim3(KPAD/32, DIM/32, BQ), dim3(32, 8)>>>(img, xh, xT);
    transpose_w_kernel<<<dim3(DIM/32, DIM/32), dim3(32, 8)>>>(w1_msg, w1T);
    transpose_w_kernel<<<dim3(DIM/32, DIM/32), dim3(32, 8)>>>(w2_msg, w2T);

    // text branch (small fp32 SIMT) — produces tq before mlp2 needs it
    gemm_kernel<1><<<dim3(12, 4, 1), 256>>>(
        text, DTXT, w1_txt, DIM, txt, DIM, BQ, DIM, DTXT, b1_txt);
    gemm_kernel<2><<<dim3(12, 4, 1), 256>>>(
        txt, DIM, w2_txt, DIM, tq, DIM, BQ, DIM, DIM, b2_txt);
    layernorm_kernel<<<BQ, 256>>>(tq, ln_w, ln_b);

    // 1) scores: S[b] = xh xh^T / sqrt(D)  -> f32 attn
    hgemm_nt<0><<<dim3(2, 2, BQ), 256>>>(
        xh, (long)NTOK*DIM, DIM,
        xh, (long)NTOK*DIM, DIM,
        attn, (long)NTOK*NTOK, NTOK,
        NTOK, NTOK, DIM, inv_sqrt_d, nullptr, nullptr, nullptr, nullptr, nullptr);

    // 2) softmax -> half attnh (K-padded)
    softmax_kernel<<<(TTOT*32 + 255)/256, 256>>>(attn, attnh);

    // 3) msg = A @ x -> half b1h
    hgemm_nt<2><<<dim3(6, 2, BQ), 256>>>(
        attnh, (long)NTOK*KPAD, KPAD,
        xT, (long)DIM*KPAD, KPAD,
        b1h, (long)NTOK*DIM, DIM,
        NTOK, DIM, KPAD, 1.f, nullptr, nullptr, nullptr, nullptr, nullptr);

    // 4) h = gelu(msg @ w1 + b1) -> half b2h
    hgemm_nt<1><<<dim3(6, TTOT/128, 1), 256>>>(
        b1h, 0, DIM, w1T, 0, DIM, b2h, 0, DIM,
        TTOT, DIM, DIM, 1.f, b1_msg, nullptr, nullptr, nullptr, nullptr);

    // 5) x_new = x + gamma_gcn*(h @ w2 + b2) -> f32 d_out (remapped) + dot accum
    hgemm_nt<3><<<dim3(6, TTOT/128, 1), 256>>>(
        b2h, 0, DIM, w2T, 0, DIM, out, 0, 0,
        TTOT, DIM, DIM, 1.f, b2_msg, img, gamma_gcn, tq, dotp);

    // 6) gating scale pass (single read+write of out token rows)
    mask_scale_kernel<<<TTOT, DIM/4>>>(out, dotp, gamma);
}

// round 11
// speedup vs baseline: 2.2955x; 1.0044x over previous
#include <cuda_runtime.h>
#include <cuda_fp16.h>
#include <cstdint>

#define BQ   256
#define NTOK 196
#define NTOT 197
#define DIM  768
#define DTXT 512
#define TTOT (BQ*NTOK)
#define KPAD 224

// ---------------- scratch (device globals) ----------------
__device__ float  g_attn [(size_t)BQ*NTOK*NTOK];
__device__ __half g_attnh[(size_t)BQ*NTOK*KPAD];
__device__ __half g_xh  [(size_t)TTOT*DIM];
__device__ __half g_xT  [(size_t)BQ*DIM*KPAD];
__device__ __half g_w1T [(size_t)DIM*DIM];
__device__ __half g_w2T [(size_t)DIM*DIM];
__device__ __half g_b1h [(size_t)TTOT*DIM];
__device__ __half g_b2h [(size_t)TTOT*DIM];
__device__ float  g_txt [(size_t)BQ*DIM];
__device__ float  g_tq  [(size_t)BQ*DIM];
__device__ float  g_dot [(size_t)TTOT];

__device__ __forceinline__ float gelu_exact(float x) { return x * normcdff(x); }

__device__ __forceinline__ void cp16(uint32_t dst, const void* src, bool ok) {
    int sz = ok ? 16 : 0;
    asm volatile("cp.async.cg.shared.global [%0], [%1], 16, %2;\n"
                 :: "r"(dst), "l"(src), "r"(sz));
}
#define CP_COMMIT() asm volatile("cp.async.commit_group;\n")
#define CP_WAIT2()  asm volatile("cp.async.wait_group 2;\n")

// =====================================================================
// fp16 NT GEMM via mma.sync: C = alpha*A(MxK)*B(NxK)^T
// A,B row-major half, K%32==0, rows 16B aligned. 128x128x32 tile,
// 8 warps (warp 64x32), 4-stage cp.async pipeline (wait_group 2),
// dynamic smem 64KB, swizzled tiles.
// MODE 0: f32 C = alpha*acc                       (scores; M,N guards)
// MODE 2: half C = acc                            (msg; M guard)
// MODE 1: half C = gelu(acc+bias)                 (mlp1; exact tiles)
// MODE 3: f32 out[remap]=resid[remap]+g*(acc+bias) + dot accum (mlp2)
// =====================================================================
#define HG_SMEM 65536
#define NSTG 4

template<int MODE>
__launch_bounds__(256, 2)
__global__ void hgemm_nt(const __half* __restrict__ A, long aBS, int lda,
                         const __half* __restrict__ B, long bBS, int ldb,
                         void* __restrict__ Cv, long cBS, int ldc,
                         int M, int N, int K, float alpha,
                         const float* __restrict__ bias,
                         const float* __restrict__ resid,
                         const float* __restrict__ gscale,
                         const float* __restrict__ tq,
                         float* __restrict__ dotp)
{
    extern __shared__ uint32_t smem_dyn[];
    uint32_t* As = smem_dyn;                    // NSTG x 2048 u32
    uint32_t* Bs = smem_dyn + NSTG * 2048;      // NSTG x 2048 u32

    const int tid  = threadIdx.x;
    const int lane = tid & 31;
    const int wid  = tid >> 5;
    const int wm   = wid & 1;
    const int wn   = wid >> 1;
    const int m0   = blockIdx.y * 128;
    const int n0   = blockIdx.x * 128;

    const __half* Ab = A + (long)blockIdx.z * aBS;
    const __half* Bb = B + (long)blockIdx.z * bBS;

    const uint32_t asb = (uint32_t)__cvta_generic_to_shared(As);
    const uint32_t bsb = (uint32_t)__cvta_generic_to_shared(Bs);

    float acc[4][4][4];
    #pragma unroll
    for (int i = 0; i < 4; i++)
        #pragma unroll
        for (int j = 0; j < 4; j++)
            #pragma unroll
            for (int r = 0; r < 4; r++) acc[i][j][r] = 0.f;

    const int ld_r  = tid >> 1;
    const int ld_hs = tid & 1;
    const int ld_sw = (ld_r >> 1) & 3;
    const int gA    = ((ld_hs*2 + 0) ^ ld_sw) << 2;
    const int gB    = ((ld_hs*2 + 1) ^ ld_sw) << 2;
    const bool okA  = (m0 + ld_r) < M;
    const bool okB  = (n0 + ld_r) < N;
    const __half* pa = Ab + (long)(okA ? (m0 + ld_r) : 0) * lda + ld_hs*16;
    const __half* pb = Bb + (long)(okB ? (n0 + ld_r) : 0) * ldb + ld_hs*16;
    const uint32_t dA0 = asb + (uint32_t)(ld_r*16 + gA) * 4;
    const uint32_t dA1 = asb + (uint32_t)(ld_r*16 + gB) * 4;
    const uint32_t dB0 = bsb + (uint32_t)(ld_r*16 + gA) * 4;
    const uint32_t dB1 = bsb + (uint32_t)(ld_r*16 + gB) * 4;

    auto load_stage = [&](int st, int k0) {
        const uint32_t so = (uint32_t)(st * 2048 * 4);
        cp16(dA0 + so, pa + k0,     okA);
        cp16(dA1 + so, pa + k0 + 8, okA);
        cp16(dB0 + so, pb + k0,     okB);
        cp16(dB1 + so, pb + k0 + 8, okB);
    };

    const int NIT = K / 32;
    // prologue: 3 stages in flight
    load_stage(0, 0); CP_COMMIT();
    if (NIT > 1) load_stage(1, 32);
    CP_COMMIT();
    if (NIT > 2) load_stage(2, 64);
    CP_COMMIT();

    const int g = lane >> 2, c = lane & 3;
    int bA0[4], bA1[4], sA0[4], sA1[4], bB[4], sB[4];
    #pragma unroll
    for (int i = 0; i < 4; i++) {
        const int r0 = wm*64 + i*16 + g;
        const int r1 = r0 + 8;
        bA0[i] = r0*16 + c;  sA0[i] = ((r0 >> 1) & 3) << 2;
        bA1[i] = r1*16 + c;  sA1[i] = ((r1 >> 1) & 3) << 2;
    }
    #pragma unroll
    for (int j = 0; j < 4; j++) {
        const int rn = wn*32 + j*8 + g;
        bB[j] = rn*16 + c;   sB[j] = ((rn >> 1) & 3) << 2;
    }

    int cur = 0;
    for (int it = 0; it < NIT; it++) {
        CP_WAIT2();
        __syncthreads();
        if (it + 3 < NIT) load_stage((it + 3) & (NSTG-1), (it + 3) * 32);
        CP_COMMIT();

        const uint32_t* Ac = As + cur * 2048;
        const uint32_t* Bc = Bs + cur * 2048;
        #pragma unroll
        for (int ks = 0; ks < 2; ks++) {
            const int kb = ks * 8;
            uint32_t af[4][4];
            #pragma unroll
            for (int i = 0; i < 4; i++) {
                af[i][0] = Ac[bA0[i] + (kb ^ sA0[i])];
                af[i][1] = Ac[bA1[i] + (kb ^ sA1[i])];
                af[i][2] = Ac[bA0[i] + ((kb + 4) ^ sA0[i])];
                af[i][3] = Ac[bA1[i] + ((kb + 4) ^ sA1[i])];
            }
            uint32_t bf[4][2];
            #pragma unroll
            for (int j = 0; j < 4; j++) {
                bf[j][0] = Bc[bB[j] + (kb ^ sB[j])];
                bf[j][1] = Bc[bB[j] + ((kb + 4) ^ sB[j])];
            }
            #pragma unroll
            for (int i = 0; i < 4; i++)
                #pragma unroll
                for (int j = 0; j < 4; j++) {
                    asm volatile(
                        "mma.sync.aligned.m16n8k16.row.col.f32.f16.f16.f32 "
                        "{%0,%1,%2,%3}, {%4,%5,%6,%7}, {%8,%9}, {%0,%1,%2,%3};\n"
                        : "+f"(acc[i][j][0]), "+f"(acc[i][j][1]),
                          "+f"(acc[i][j][2]), "+f"(acc[i][j][3])
                        : "r"(af[i][0]), "r"(af[i][1]), "r"(af[i][2]), "r"(af[i][3]),
                          "r"(bf[j][0]), "r"(bf[j][1]));
                }
        }
        cur = (cur + 1) & (NSTG-1);
    }

    // ---------------- epilogue ----------------
    const int tg = lane & 3;

    if (MODE == 0) {            // scores: f32 = alpha*acc, M/N guards
        float* Cf = reinterpret_cast<float*>(Cv) + (long)blockIdx.z * cBS;
        #pragma unroll
        for (int i = 0; i < 4; i++)
            #pragma unroll
            for (int hi = 0; hi < 2; hi++) {
                const int row = m0 + wm*64 + i*16 + g + 8*hi;
                if (row >= M) continue;
                #pragma unroll
                for (int j = 0; j < 4; j++) {
                    const int col = n0 + wn*32 + j*8 + tg*2;
                    if (col >= N) continue;
                    float2 o = make_float2(acc[i][j][2*hi+0] * alpha,
                                           acc[i][j][2*hi+1] * alpha);
                    *reinterpret_cast<float2*>(Cf + (long)row*ldc + col) = o;
                }
            }
    } else if (MODE == 2) {     // msg: half = acc, M guard only
        __half* Ch = reinterpret_cast<__half*>(Cv) + (long)blockIdx.z * cBS;
        #pragma unroll
        for (int i = 0; i < 4; i++)
            #pragma unroll
            for (int hi = 0; hi < 2; hi++) {
                const int row = m0 + wm*64 + i*16 + g + 8*hi;
                if (row >= M) continue;
                #pragma unroll
                for (int j = 0; j < 4; j++) {
                    const int col = n0 + wn*32 + j*8 + tg*2;
                    *reinterpret_cast<__half2*>(Ch + (long)row*ldc + col) =
                        __floats2half2_rn(acc[i][j][2*hi+0], acc[i][j][2*hi+1]);
                }
            }
    } else if (MODE == 1) {     // mlp1: half = gelu(acc+bias), exact tiles
        __half* Ch = reinterpret_cast<__half*>(Cv);
        #pragma unroll
        for (int i = 0; i < 4; i++)
            #pragma unroll
            for (int hi = 0; hi < 2; hi++) {
                const int row = m0 + wm*64 + i*16 + g + 8*hi;
                #pragma unroll
                for (int j = 0; j < 4; j++) {
                    const int col = n0 + wn*32 + j*8 + tg*2;
                    float v0 = gelu_exact(acc[i][j][2*hi+0] + bias[col]);
                    float v1 = gelu_exact(acc[i][j][2*hi+1] + bias[col+1]);
                    *reinterpret_cast<__half2*>(Ch + (long)row*ldc + col) =
                        __floats2half2_rn(v0, v1);
                }
            }
    } else {                    // mlp2: residual+remap + dot accumulation
        float* Cf = reinterpret_cast<float*>(Cv);
        const float gsc = gscale[0];
        #pragma unroll
        for (int i = 0; i < 4; i++)
            #pragma unroll
            for (int hi = 0; hi < 2; hi++) {
                const int row = m0 + wm*64 + i*16 + g + 8*hi;   // token index
                const int b   = row / NTOK;
                const int rr  = row - b * NTOK;
                const long off = ((long)b * NTOT + 1 + rr) * DIM;
                const float* tqr = tq + (long)b * DIM;
                float part = 0.f;
                #pragma unroll
                for (int j = 0; j < 4; j++) {
                    const int col = n0 + wn*32 + j*8 + tg*2;
                    float2 rv = *reinterpret_cast<const float2*>(resid + off + col);
                    float2 tv = *reinterpret_cast<const float2*>(tqr + col);
                    float o0 = rv.x + gsc * (acc[i][j][2*hi+0] + bias[col]);
                    float o1 = rv.y + gsc * (acc[i][j][2*hi+1] + bias[col+1]);
                    *reinterpret_cast<float2*>(Cf + off + col) = make_float2(o0, o1);
                    part += o0 * tv.x + o1 * tv.y;
                }
                // pre-reduce across the 4 lanes (tg=0..3) that share this row
                part += __shfl_xor_sync(0xffffffffu, part, 1);
                part += __shfl_xor_sync(0xffffffffu, part, 2);
                if (tg == 0) atomicAdd(dotp + row, part);
            }
    }
}

// ------- fused pre-pass: img tokens -> xh (row-major half) + xT (half^T) -----
__global__ void prep_x_kernel(const float* __restrict__ img,
                              __half* __restrict__ xh, __half* __restrict__ xT)
{
    __shared__ float tile[32][33];
    const int b  = blockIdx.z;
    const int t0 = blockIdx.x * 32;
    const int d0 = blockIdx.y * 32;
    #pragma unroll
    for (int i = threadIdx.y; i < 32; i += 8) {
        const int t = t0 + i;
        float v = 0.f;
        if (t < NTOK) {
            v = img[((long)b*NTOT + 1 + t)*DIM + d0 + threadIdx.x];
            xh[((long)b*NTOK + t)*DIM + d0 + threadIdx.x] = __float2half_rn(v);
        }
        tile[i][threadIdx.x] = v;
    }
    __syncthreads();
    #pragma unroll
    for (int i = threadIdx.y; i < 32; i += 8) {
        const int d = d0 + i;
        xT[((long)b*DIM + d)*KPAD + t0 + threadIdx.x] =
            __float2half_rn(tile[threadIdx.x][i]);
    }
}

// ----- pre-pass: both weight transposes in one launch (z selects matrix) -----
__global__ void transpose_w2_kernel(const float* __restrict__ w1, __half* __restrict__ w1T,
                                    const float* __restrict__ w2, __half* __restrict__ w2T)
{
    __shared__ float tile[32][33];
    const float* w  = blockIdx.z ? w2  : w1;
    __half*      wT = blockIdx.z ? w2T : w1T;
    const int k0 = blockIdx.x * 32;
    const int n0 = blockIdx.y * 32;
    #pragma unroll
    for (int i = threadIdx.y; i < 32; i += 8)
        tile[i][threadIdx.x] = w[(long)(k0+i)*DIM + n0 + threadIdx.x];
    __syncthreads();
    #pragma unroll
    for (int i = threadIdx.y; i < 32; i += 8)
        wT[(long)(n0+i)*DIM + k0 + threadIdx.x] = __float2half_rn(tile[threadIdx.x][i]);
}

// ------- softmax rows of g_attn -> half g_attnh (stride KPAD, zero-pad) -----
__global__ void softmax_kernel(const float* __restrict__ S, __half* __restrict__ Sh)
{
    int warp = (blockIdx.x * blockDim.x + threadIdx.x) >> 5;
    int lane = threadIdx.x & 31;
    if (warp >= (int)(BQ * NTOK)) return;
    const float* p = S + (long)warp * NTOK;
    __half* ph = Sh + (long)warp * KPAD;

    float v[7], mx = -3.0e38f;
    #pragma unroll
    for (int it = 0; it < 7; it++) {
        int j = lane + it*32;
        v[it] = (j < NTOK) ? p[j] : -3.0e38f;
        mx = fmaxf(mx, v[it]);
    }
    #pragma unroll
    for (int o = 16; o; o >>= 1) mx = fmaxf(mx, __shfl_xor_sync(0xffffffffu, mx, o));
    float s = 0.f;
    #pragma unroll
    for (int it = 0; it < 7; it++) {
        int j = lane + it*32;
        if (j < NTOK) { v[it] = expf(v[it]-mx); s += v[it]; } else v[it] = 0.f;
    }
    #pragma unroll
    for (int o = 16; o; o >>= 1) s += __shfl_xor_sync(0xffffffffu, s, o);
    float inv = 1.f / s;
    #pragma unroll
    for (int it = 0; it < 7; it++) {
        int j = lane + it*32;
        ph[j] = __float2half_rn((j < NTOK) ? v[it]*inv : 0.f);
    }
}

// ---------------- SIMT fp32 GEMM (tiny text-branch) --------------------------
template<int MODE>
__launch_bounds__(256)
__global__ void gemm_kernel(const float* __restrict__ A, int lda,
                            const float* __restrict__ B, int ldb,
                            float* __restrict__ C, int ldc,
                            int M, int N, int K,
                            const float* __restrict__ bias)
{
    const int BM = 64, BN = 64, BK = 16;
    __shared__ float Ast[BK][BM + 4];
    __shared__ float Bst[BK][BN];
    const int tid = threadIdx.x;
    const int tx = tid & 15, ty = tid >> 4;
    const int m0 = blockIdx.y * BM, n0 = blockIdx.x * BN;
    float acc[4][4] = {};
    const int aRow = tid >> 2, aCol = (tid & 3) * 4;

    for (int k0 = 0; k0 < K; k0 += BK) {
        {
            float4 v = make_float4(0.f,0.f,0.f,0.f);
            int gr = m0 + aRow;
            if (gr < M) {
                int gc = k0 + aCol;
                if (gc + 3 < K) v = *reinterpret_cast<const float4*>(A + (long)gr*lda + gc);
            }
            Ast[aCol+0][aRow]=v.x; Ast[aCol+1][aRow]=v.y;
            Ast[aCol+2][aRow]=v.z; Ast[aCol+3][aRow]=v.w;
        }
        {
            int br = tid >> 4, bc = (tid & 15) * 4;
            float4 v = make_float4(0.f,0.f,0.f,0.f);
            int gk = k0 + br, gn = n0 + bc;
            if (gk < K && gn + 3 < N)
                v = *reinterpret_cast<const float4*>(B + (long)gk*ldb + gn);
            *reinterpret_cast<float4*>(&Bst[br][bc]) = v;
        }
        __syncthreads();
        #pragma unroll
        for (int k = 0; k < BK; k++) {
            float4 av = *reinterpret_cast<const float4*>(&Ast[k][ty*4]);
            float4 bv = *reinterpret_cast<const float4*>(&Bst[k][tx*4]);
            acc[0][0]+=av.x*bv.x; acc[0][1]+=av.x*bv.y; acc[0][2]+=av.x*bv.z; acc[0][3]+=av.x*bv.w;
            acc[1][0]+=av.y*bv.x; acc[1][1]+=av.y*bv.y; acc[1][2]+=av.y*bv.z; acc[1][3]+=av.y*bv.w;
            acc[2][0]+=av.z*bv.x; acc[2][1]+=av.z*bv.y; acc[2][2]+=av.z*bv.z; acc[2][3]+=av.z*bv.w;
            acc[3][0]+=av.w*bv.x; acc[3][1]+=av.w*bv.y; acc[3][2]+=av.w*bv.z; acc[3][3]+=av.w*bv.w;
        }
        __syncthreads();
    }
    #pragma unroll
    for (int i = 0; i < 4; i++) {
        int m = m0 + ty*4 + i; if (m >= M) continue;
        #pragma unroll
        for (int j = 0; j < 4; j++) {
            int n = n0 + tx*4 + j; if (n >= N) continue;
            float v = acc[i][j] + bias[n];
            if (MODE == 1) v = gelu_exact(v);
            C[(long)m*ldc + n] = v;
        }
    }
}

__global__ void layernorm_kernel(float* __restrict__ X,
                                 const float* __restrict__ w,
                                 const float* __restrict__ b)
{
    int row = blockIdx.x;
    float* p = X + (long)row * DIM;
    float s = 0.f, sq = 0.f;
    for (int j = threadIdx.x; j < DIM; j += blockDim.x) {
        float x = p[j]; s += x; sq += x*x;
    }
    __shared__ float rs[32], rq[32];
    int lane = threadIdx.x & 31, wd = threadIdx.x >> 5;
    #pragma unroll
    for (int o = 16; o; o >>= 1) {
        s  += __shfl_xor_sync(0xffffffffu, s, o);
        sq += __shfl_xor_sync(0xffffffffu, sq, o);
    }
    if (lane == 0) { rs[wd] = s; rq[wd] = sq; }
    __syncthreads();
    int nw = blockDim.x >> 5;
    if (wd == 0) {
        float a = (lane < nw) ? rs[lane] : 0.f;
        float cc = (lane < nw) ? rq[lane] : 0.f;
        #pragma unroll
        for (int o = 16; o; o >>= 1) {
            a  += __shfl_xor_sync(0xffffffffu, a, o);
            cc += __shfl_xor_sync(0xffffffffu, cc, o);
        }
        if (lane == 0) { rs[0] = a; rq[0] = cc; }
    }
    __syncthreads();
    float mu = rs[0] / DIM;
    float var = rq[0] / DIM - mu*mu;
    float rstd = rsqrtf(var + 1e-5f);
    for (int j = threadIdx.x; j < DIM; j += blockDim.x)
        p[j] = (p[j]-mu)*rstd*w[j] + b[j];
}

// ----- gating scale pass: out_row *= (1 + gamma*sigmoid(dot[row])) -----------
__global__ void mask_scale_kernel(float* __restrict__ out,
                                  const float* __restrict__ dotp,
                                  const float* __restrict__ gamma)
{
    const int t = blockIdx.x;
    const int b = t / NTOK, r = t - b*NTOK;
    const float sc = 1.f + gamma[0] / (1.f + expf(-dotp[t]));
    float4* p = reinterpret_cast<float4*>(out + ((long)b*NTOT + 1 + r)*DIM);
    const int j = threadIdx.x;                // blockDim = 192 = DIM/4
    float4 v = p[j];
    v.x *= sc; v.y *= sc; v.z *= sc; v.w *= sc;
    p[j] = v;
}

__global__ void copy_cls_kernel(const float* __restrict__ img, float* __restrict__ out)
{
    long base = (long)blockIdx.x * NTOT * DIM;
    for (int j = threadIdx.x; j < DIM; j += blockDim.x)
        out[base + j] = img[base + j];
}

// =====================================================================
extern "C" void kernel_launch(void* const* d_in, const int* in_sizes, int n_in,
                              void* d_out, int out_size)
{
    const float* img       = (const float*)d_in[0];
    const float* text      = (const float*)d_in[1];
    const float* w1_msg    = (const float*)d_in[2];
    const float* b1_msg    = (const float*)d_in[3];
    const float* w2_msg    = (const float*)d_in[4];
    const float* b2_msg    = (const float*)d_in[5];
    const float* gamma_gcn = (const float*)d_in[6];
    const float* w1_txt    = (const float*)d_in[7];
    const float* b1_txt    = (const float*)d_in[8];
    const float* w2_txt    = (const float*)d_in[9];
    const float* b2_txt    = (const float*)d_in[10];
    const float* ln_w      = (const float*)d_in[11];
    const float* ln_b      = (const float*)d_in[12];
    const float* gamma     = (const float*)d_in[13];
    float* out = (float*)d_out;

    float *attn, *txt, *tq, *dotp;
    __half *attnh, *xh, *xT, *w1T, *w2T, *b1h, *b2h;
    cudaGetSymbolAddress((void**)&attn,  g_attn);
    cudaGetSymbolAddress((void**)&attnh, g_attnh);
    cudaGetSymbolAddress((void**)&xh,    g_xh);
    cudaGetSymbolAddress((void**)&xT,    g_xT);
    cudaGetSymbolAddress((void**)&w1T,   g_w1T);
    cudaGetSymbolAddress((void**)&w2T,   g_w2T);
    cudaGetSymbolAddress((void**)&b1h,   g_b1h);
    cudaGetSymbolAddress((void**)&b2h,   g_b2h);
    cudaGetSymbolAddress((void**)&txt,   g_txt);
    cudaGetSymbolAddress((void**)&tq,    g_tq);
    cudaGetSymbolAddress((void**)&dotp,  g_dot);

    // opt-in >48KB dynamic smem (idempotent; no allocation)
    cudaFuncSetAttribute(hgemm_nt<0>, cudaFuncAttributeMaxDynamicSharedMemorySize, HG_SMEM);
    cudaFuncSetAttribute(hgemm_nt<1>, cudaFuncAttributeMaxDynamicSharedMemorySize, HG_SMEM);
    cudaFuncSetAttribute(hgemm_nt<2>, cudaFuncAttributeMaxDynamicSharedMemorySize, HG_SMEM);
    cudaFuncSetAttribute(hgemm_nt<3>, cudaFuncAttributeMaxDynamicSharedMemorySize, HG_SMEM);

    const float inv_sqrt_d = 0.03608439182435161f;  // 1/sqrt(768)

    // zero the dot accumulator (graph-capturable async memset)
    cudaMemsetAsync(dotp, 0, (size_t)TTOT * sizeof(float));

    // pre-passes (independent)
    copy_cls_kernel<<<BQ, 256>>>(img, out);
    prep_x_kernel<<<dim3(KPAD/32, DIM/32, BQ), dim3(32, 8)>>>(img, xh, xT);
    transpose_w2_kernel<<<dim3(DIM/32, DIM/32, 2), dim3(32, 8)>>>(w1_msg, w1T, w2_msg, w2T);

    // text branch (small fp32 SIMT) — produces tq before mlp2 needs it
    gemm_kernel<1><<<dim3(12, 4, 1), 256>>>(
        text, DTXT, w1_txt, DIM, txt, DIM, BQ, DIM, DTXT, b1_txt);
    gemm_kernel<2><<<dim3(12, 4, 1), 256>>>(
        txt, DIM, w2_txt, DIM, tq, DIM, BQ, DIM, DIM, b2_txt);
    layernorm_kernel<<<BQ, 256>>>(tq, ln_w, ln_b);

    // 1) scores: S[b] = xh xh^T / sqrt(D)  -> f32 attn
    hgemm_nt<0><<<dim3(2, 2, BQ), 256, HG_SMEM>>>(
        xh, (long)NTOK*DIM, DIM,
        xh, (long)NTOK*DIM, DIM,
        attn, (long)NTOK*NTOK, NTOK,
        NTOK, NTOK, DIM, inv_sqrt_d, nullptr, nullptr, nullptr, nullptr, nullptr);

    // 2) softmax -> half attnh (K-padded)
    softmax_kernel<<<(TTOT*32 + 255)/256, 256>>>(attn, attnh);

    // 3) msg = A @ x -> half b1h
    hgemm_nt<2><<<dim3(6, 2, BQ), 256, HG_SMEM>>>(
        attnh, (long)NTOK*KPAD, KPAD,
        xT, (long)DIM*KPAD, KPAD,
        b1h, (long)NTOK*DIM, DIM,
        NTOK, DIM, KPAD, 1.f, nullptr, nullptr, nullptr, nullptr, nullptr);

    // 4) h = gelu(msg @ w1 + b1) -> half b2h
    hgemm_nt<1><<<dim3(6, TTOT/128, 1), 256, HG_SMEM>>>(
        b1h, 0, DIM, w1T, 0, DIM, b2h, 0, DIM,
        TTOT, DIM, DIM, 1.f, b1_msg, nullptr, nullptr, nullptr, nullptr);

    // 5) x_new = x + gamma_gcn*(h @ w2 + b2) -> f32 d_out (remapped) + dot accum
    hgemm_nt<3><<<dim3(6, TTOT/128, 1), 256, HG_SMEM>>>(
        b2h, 0, DIM, w2T, 0, DIM, out, 0, 0,
        TTOT, DIM, DIM, 1.f, b2_msg, img, gamma_gcn, tq, dotp);

    // 6) gating scale pass (single read+write of out token rows)
    mask_scale_kernel<<<TTOT, DIM/4>>>(out, dotp, gamma);
}

// round 12
// speedup vs baseline: 2.4183x; 1.0535x over previous
#include <cuda_runtime.h>
#include <cuda_fp16.h>
#include <cstdint>

#define BQ   256
#define NTOK 196
#define NTOT 197
#define DIM  768
#define DTXT 512
#define TTOT (BQ*NTOK)
#define KPAD 224

// ---------------- scratch (device globals) ----------------
__device__ float  g_attn [(size_t)BQ*NTOK*NTOK];
__device__ __half g_attnh[(size_t)BQ*NTOK*KPAD];
__device__ __half g_xh  [(size_t)TTOT*DIM];
__device__ __half g_xT  [(size_t)BQ*DIM*KPAD];
__device__ __half g_w1T [(size_t)DIM*DIM];
__device__ __half g_w2T [(size_t)DIM*DIM];
__device__ __half g_b1h [(size_t)TTOT*DIM];
__device__ __half g_b2h [(size_t)TTOT*DIM];
__device__ __half g_texth[(size_t)BQ*DTXT];     // text, half
__device__ __half g_w1tT [(size_t)DIM*DTXT];    // w1_txt^T, half (768x512)
__device__ __half g_w2tT [(size_t)DIM*DIM];     // w2_txt^T, half
__device__ __half g_txth [(size_t)BQ*DIM];      // gelu(text@w1+b1), half
__device__ float  g_tq  [(size_t)BQ*DIM];
__device__ float  g_dot [(size_t)TTOT];

__device__ __forceinline__ float gelu_exact(float x) { return x * normcdff(x); }

__device__ __forceinline__ void cp16(uint32_t dst, const void* src, bool ok) {
    int sz = ok ? 16 : 0;
    asm volatile("cp.async.cg.shared.global [%0], [%1], 16, %2;\n"
                 :: "r"(dst), "l"(src), "r"(sz));
}
#define CP_COMMIT() asm volatile("cp.async.commit_group;\n")
#define CP_WAIT2()  asm volatile("cp.async.wait_group 2;\n")

// =====================================================================
// fp16 NT GEMM via mma.sync: C = alpha*A(MxK)*B(NxK)^T
// A,B row-major half, K%32==0, rows 16B aligned. 128x128x32 tile,
// 8 warps (warp 64x32), 4-stage cp.async pipeline (wait_group 2),
// dynamic smem 64KB, swizzled tiles.
// MODE 0: f32 C = alpha*acc                       (scores; M,N guards)
// MODE 2: half C = acc                            (msg; M guard)
// MODE 1: half C = gelu(acc+bias)                 (mlp1/text1; exact tiles)
// MODE 4: f32 C = acc + bias                      (text2; exact tiles)
// MODE 3: f32 out[remap]=resid[remap]+g*(acc+bias) + dot accum (mlp2)
// =====================================================================
#define HG_SMEM 65536
#define NSTG 4

template<int MODE>
__launch_bounds__(256, 2)
__global__ void hgemm_nt(const __half* __restrict__ A, long aBS, int lda,
                         const __half* __restrict__ B, long bBS, int ldb,
                         void* __restrict__ Cv, long cBS, int ldc,
                         int M, int N, int K, float alpha,
                         const float* __restrict__ bias,
                         const float* __restrict__ resid,
                         const float* __restrict__ gscale,
                         const float* __restrict__ tq,
                         float* __restrict__ dotp)
{
    extern __shared__ uint32_t smem_dyn[];
    uint32_t* As = smem_dyn;                    // NSTG x 2048 u32
    uint32_t* Bs = smem_dyn + NSTG * 2048;      // NSTG x 2048 u32

    const int tid  = threadIdx.x;
    const int lane = tid & 31;
    const int wid  = tid >> 5;
    const int wm   = wid & 1;
    const int wn   = wid >> 1;
    const int m0   = blockIdx.y * 128;
    const int n0   = blockIdx.x * 128;

    const __half* Ab = A + (long)blockIdx.z * aBS;
    const __half* Bb = B + (long)blockIdx.z * bBS;

    const uint32_t asb = (uint32_t)__cvta_generic_to_shared(As);
    const uint32_t bsb = (uint32_t)__cvta_generic_to_shared(Bs);

    float acc[4][4][4];
    #pragma unroll
    for (int i = 0; i < 4; i++)
        #pragma unroll
        for (int j = 0; j < 4; j++)
            #pragma unroll
            for (int r = 0; r < 4; r++) acc[i][j][r] = 0.f;

    const int ld_r  = tid >> 1;
    const int ld_hs = tid & 1;
    const int ld_sw = (ld_r >> 1) & 3;
    const int gA    = ((ld_hs*2 + 0) ^ ld_sw) << 2;
    const int gB    = ((ld_hs*2 + 1) ^ ld_sw) << 2;
    const bool okA  = (m0 + ld_r) < M;
    const bool okB  = (n0 + ld_r) < N;
    const __half* pa = Ab + (long)(okA ? (m0 + ld_r) : 0) * lda + ld_hs*16;
    const __half* pb = Bb + (long)(okB ? (n0 + ld_r) : 0) * ldb + ld_hs*16;
    const uint32_t dA0 = asb + (uint32_t)(ld_r*16 + gA) * 4;
    const uint32_t dA1 = asb + (uint32_t)(ld_r*16 + gB) * 4;
    const uint32_t dB0 = bsb + (uint32_t)(ld_r*16 + gA) * 4;
    const uint32_t dB1 = bsb + (uint32_t)(ld_r*16 + gB) * 4;

    auto load_stage = [&](int st, int k0) {
        const uint32_t so = (uint32_t)(st * 2048 * 4);
        cp16(dA0 + so, pa + k0,     okA);
        cp16(dA1 + so, pa + k0 + 8, okA);
        cp16(dB0 + so, pb + k0,     okB);
        cp16(dB1 + so, pb + k0 + 8, okB);
    };

    const int NIT = K / 32;
    load_stage(0, 0); CP_COMMIT();
    if (NIT > 1) load_stage(1, 32);
    CP_COMMIT();
    if (NIT > 2) load_stage(2, 64);
    CP_COMMIT();

    const int g = lane >> 2, c = lane & 3;
    int bA0[4], bA1[4], sA0[4], sA1[4], bB[4], sB[4];
    #pragma unroll
    for (int i = 0; i < 4; i++) {
        const int r0 = wm*64 + i*16 + g;
        const int r1 = r0 + 8;
        bA0[i] = r0*16 + c;  sA0[i] = ((r0 >> 1) & 3) << 2;
        bA1[i] = r1*16 + c;  sA1[i] = ((r1 >> 1) & 3) << 2;
    }
    #pragma unroll
    for (int j = 0; j < 4; j++) {
        const int rn = wn*32 + j*8 + g;
        bB[j] = rn*16 + c;   sB[j] = ((rn >> 1) & 3) << 2;
    }

    int cur = 0;
    for (int it = 0; it < NIT; it++) {
        CP_WAIT2();
        __syncthreads();
        if (it + 3 < NIT) load_stage((it + 3) & (NSTG-1), (it + 3) * 32);
        CP_COMMIT();

        const uint32_t* Ac = As + cur * 2048;
        const uint32_t* Bc = Bs + cur * 2048;
        #pragma unroll
        for (int ks = 0; ks < 2; ks++) {
            const int kb = ks * 8;
            uint32_t af[4][4];
            #pragma unroll
            for (int i = 0; i < 4; i++) {
                af[i][0] = Ac[bA0[i] + (kb ^ sA0[i])];
                af[i][1] = Ac[bA1[i] + (kb ^ sA1[i])];
                af[i][2] = Ac[bA0[i] + ((kb + 4) ^ sA0[i])];
                af[i][3] = Ac[bA1[i] + ((kb + 4) ^ sA1[i])];
            }
            uint32_t bf[4][2];
            #pragma unroll
            for (int j = 0; j < 4; j++) {
                bf[j][0] = Bc[bB[j] + (kb ^ sB[j])];
                bf[j][1] = Bc[bB[j] + ((kb + 4) ^ sB[j])];
            }
            #pragma unroll
            for (int i = 0; i < 4; i++)
                #pragma unroll
                for (int j = 0; j < 4; j++) {
                    asm volatile(
                        "mma.sync.aligned.m16n8k16.row.col.f32.f16.f16.f32 "
                        "{%0,%1,%2,%3}, {%4,%5,%6,%7}, {%8,%9}, {%0,%1,%2,%3};\n"
                        : "+f"(acc[i][j][0]), "+f"(acc[i][j][1]),
                          "+f"(acc[i][j][2]), "+f"(acc[i][j][3])
                        : "r"(af[i][0]), "r"(af[i][1]), "r"(af[i][2]), "r"(af[i][3]),
                          "r"(bf[j][0]), "r"(bf[j][1]));
                }
        }
        cur = (cur + 1) & (NSTG-1);
    }

    // ---------------- epilogue ----------------
    const int tg = lane & 3;

    if (MODE == 0) {            // scores: f32 = alpha*acc, M/N guards
        float* Cf = reinterpret_cast<float*>(Cv) + (long)blockIdx.z * cBS;
        #pragma unroll
        for (int i = 0; i < 4; i++)
            #pragma unroll
            for (int hi = 0; hi < 2; hi++) {
                const int row = m0 + wm*64 + i*16 + g + 8*hi;
                if (row >= M) continue;
                #pragma unroll
                for (int j = 0; j < 4; j++) {
                    const int col = n0 + wn*32 + j*8 + tg*2;
                    if (col >= N) continue;
                    float2 o = make_float2(acc[i][j][2*hi+0] * alpha,
                                           acc[i][j][2*hi+1] * alpha);
                    *reinterpret_cast<float2*>(Cf + (long)row*ldc + col) = o;
                }
            }
    } else if (MODE == 2) {     // msg: half = acc, M guard only
        __half* Ch = reinterpret_cast<__half*>(Cv) + (long)blockIdx.z * cBS;
        #pragma unroll
        for (int i = 0; i < 4; i++)
            #pragma unroll
            for (int hi = 0; hi < 2; hi++) {
                const int row = m0 + wm*64 + i*16 + g + 8*hi;
                if (row >= M) continue;
                #pragma unroll
                for (int j = 0; j < 4; j++) {
                    const int col = n0 + wn*32 + j*8 + tg*2;
                    *reinterpret_cast<__half2*>(Ch + (long)row*ldc + col) =
                        __floats2half2_rn(acc[i][j][2*hi+0], acc[i][j][2*hi+1]);
                }
            }
    } else if (MODE == 1) {     // half = gelu(acc+bias), exact tiles
        __half* Ch = reinterpret_cast<__half*>(Cv);
        #pragma unroll
        for (int i = 0; i < 4; i++)
            #pragma unroll
            for (int hi = 0; hi < 2; hi++) {
                const int row = m0 + wm*64 + i*16 + g + 8*hi;
                #pragma unroll
                for (int j = 0; j < 4; j++) {
                    const int col = n0 + wn*32 + j*8 + tg*2;
                    float v0 = gelu_exact(acc[i][j][2*hi+0] + bias[col]);
                    float v1 = gelu_exact(acc[i][j][2*hi+1] + bias[col+1]);
                    *reinterpret_cast<__half2*>(Ch + (long)row*ldc + col) =
                        __floats2half2_rn(v0, v1);
                }
            }
    } else if (MODE == 4) {     // f32 = acc + bias, exact tiles
        float* Cf = reinterpret_cast<float*>(Cv);
        #pragma unroll
        for (int i = 0; i < 4; i++)
            #pragma unroll
            for (int hi = 0; hi < 2; hi++) {
                const int row = m0 + wm*64 + i*16 + g + 8*hi;
                #pragma unroll
                for (int j = 0; j < 4; j++) {
                    const int col = n0 + wn*32 + j*8 + tg*2;
                    float2 o = make_float2(acc[i][j][2*hi+0] + bias[col],
                                           acc[i][j][2*hi+1] + bias[col+1]);
                    *reinterpret_cast<float2*>(Cf + (long)row*ldc + col) = o;
                }
            }
    } else {                    // mlp2: residual+remap + dot accumulation
        float* Cf = reinterpret_cast<float*>(Cv);
        const float gsc = gscale[0];
        #pragma unroll
        for (int i = 0; i < 4; i++)
            #pragma unroll
            for (int hi = 0; hi < 2; hi++) {
                const int row = m0 + wm*64 + i*16 + g + 8*hi;   // token index
                const int b   = row / NTOK;
                const int rr  = row - b * NTOK;
                const long off = ((long)b * NTOT + 1 + rr) * DIM;
                const float* tqr = tq + (long)b * DIM;
                float part = 0.f;
                #pragma unroll
                for (int j = 0; j < 4; j++) {
                    const int col = n0 + wn*32 + j*8 + tg*2;
                    float2 rv = *reinterpret_cast<const float2*>(resid + off + col);
                    float2 tv = *reinterpret_cast<const float2*>(tqr + col);
                    float o0 = rv.x + gsc * (acc[i][j][2*hi+0] + bias[col]);
                    float o1 = rv.y + gsc * (acc[i][j][2*hi+1] + bias[col+1]);
                    *reinterpret_cast<float2*>(Cf + off + col) = make_float2(o0, o1);
                    part += o0 * tv.x + o1 * tv.y;
                }
                part += __shfl_xor_sync(0xffffffffu, part, 1);
                part += __shfl_xor_sync(0xffffffffu, part, 2);
                if (tg == 0) atomicAdd(dotp + row, part);
            }
    }
}

// ------- fused pre-pass: img tokens -> xh (row-major half) + xT (half^T) -----
__global__ void prep_x_kernel(const float* __restrict__ img,
                              __half* __restrict__ xh, __half* __restrict__ xT)
{
    __shared__ float tile[32][33];
    const int b  = blockIdx.z;
    const int t0 = blockIdx.x * 32;
    const int d0 = blockIdx.y * 32;
    #pragma unroll
    for (int i = threadIdx.y; i < 32; i += 8) {
        const int t = t0 + i;
        float v = 0.f;
        if (t < NTOK) {
            v = img[((long)b*NTOT + 1 + t)*DIM + d0 + threadIdx.x];
            xh[((long)b*NTOK + t)*DIM + d0 + threadIdx.x] = __float2half_rn(v);
        }
        tile[i][threadIdx.x] = v;
    }
    __syncthreads();
    #pragma unroll
    for (int i = threadIdx.y; i < 32; i += 8) {
        const int d = d0 + i;
        xT[((long)b*DIM + d)*KPAD + t0 + threadIdx.x] =
            __float2half_rn(tile[threadIdx.x][i]);
    }
}

// ----- pre-pass: all 4 weight transposes in one launch (z selects matrix) ----
// w is R x 768 row-major f32; wT is 768 x R row-major half.
__global__ void transpose_all_kernel(
    const float* __restrict__ w1m, __half* __restrict__ w1mT,
    const float* __restrict__ w2m, __half* __restrict__ w2mT,
    const float* __restrict__ w1t, __half* __restrict__ w1tT,
    const float* __restrict__ w2t, __half* __restrict__ w2tT)
{
    __shared__ float tile[32][33];
    const float* W; __half* WT; int R;
    switch (blockIdx.z) {
        case 0:  W = w1m; WT = w1mT; R = DIM;  break;
        case 1:  W = w2m; WT = w2mT; R = DIM;  break;
        case 2:  W = w1t; WT = w1tT; R = DTXT; break;
        default: W = w2t; WT = w2tT; R = DIM;  break;
    }
    const int k0 = blockIdx.x * 32;
    if (k0 >= R) return;
    const int n0 = blockIdx.y * 32;
    #pragma unroll
    for (int i = threadIdx.y; i < 32; i += 8)
        tile[i][threadIdx.x] = W[(long)(k0+i)*DIM + n0 + threadIdx.x];
    __syncthreads();
    #pragma unroll
    for (int i = threadIdx.y; i < 32; i += 8)
        WT[(long)(n0+i)*R + k0 + threadIdx.x] = __float2half_rn(tile[threadIdx.x][i]);
}

// ---------------- pre-pass: text f32 -> half ---------------------------------
__global__ void conv_text_kernel(const float* __restrict__ text, __half* __restrict__ th)
{
    const long base = (long)blockIdx.x * DTXT;
    const float2* src = reinterpret_cast<const float2*>(text + base);
    __half2* dst = reinterpret_cast<__half2*>(th + base);
    dst[threadIdx.x] = __float22half2_rn(src[threadIdx.x]);   // blockDim = DTXT/2
}

// ------- softmax rows of g_attn -> half g_attnh (stride KPAD, zero-pad) -----
__global__ void softmax_kernel(const float* __restrict__ S, __half* __restrict__ Sh)
{
    int warp = (blockIdx.x * blockDim.x + threadIdx.x) >> 5;
    int lane = threadIdx.x & 31;
    if (warp >= (int)(BQ * NTOK)) return;
    const float* p = S + (long)warp * NTOK;
    __half* ph = Sh + (long)warp * KPAD;

    float v[7], mx = -3.0e38f;
    #pragma unroll
    for (int it = 0; it < 7; it++) {
        int j = lane + it*32;
        v[it] = (j < NTOK) ? p[j] : -3.0e38f;
        mx = fmaxf(mx, v[it]);
    }
    #pragma unroll
    for (int o = 16; o; o >>= 1) mx = fmaxf(mx, __shfl_xor_sync(0xffffffffu, mx, o));
    float s = 0.f;
    #pragma unroll
    for (int it = 0; it < 7; it++) {
        int j = lane + it*32;
        if (j < NTOK) { v[it] = expf(v[it]-mx); s += v[it]; } else v[it] = 0.f;
    }
    #pragma unroll
    for (int o = 16; o; o >>= 1) s += __shfl_xor_sync(0xffffffffu, s, o);
    float inv = 1.f / s;
    #pragma unroll
    for (int it = 0; it < 7; it++) {
        int j = lane + it*32;
        ph[j] = __float2half_rn((j < NTOK) ? v[it]*inv : 0.f);
    }
}

__global__ void layernorm_kernel(float* __restrict__ X,
                                 const float* __restrict__ w,
                                 const float* __restrict__ b)
{
    int row = blockIdx.x;
    float* p = X + (long)row * DIM;
    float s = 0.f, sq = 0.f;
    for (int j = threadIdx.x; j < DIM; j += blockDim.x) {
        float x = p[j]; s += x; sq += x*x;
    }
    __shared__ float rs[32], rq[32];
    int lane = threadIdx.x & 31, wd = threadIdx.x >> 5;
    #pragma unroll
    for (int o = 16; o; o >>= 1) {
        s  += __shfl_xor_sync(0xffffffffu, s, o);
        sq += __shfl_xor_sync(0xffffffffu, sq, o);
    }
    if (lane == 0) { rs[wd] = s; rq[wd] = sq; }
    __syncthreads();
    int nw = blockDim.x >> 5;
    if (wd == 0) {
        float a = (lane < nw) ? rs[lane] : 0.f;
        float cc = (lane < nw) ? rq[lane] : 0.f;
        #pragma unroll
        for (int o = 16; o; o >>= 1) {
            a  += __shfl_xor_sync(0xffffffffu, a, o);
            cc += __shfl_xor_sync(0xffffffffu, cc, o);
        }
        if (lane == 0) { rs[0] = a; rq[0] = cc; }
    }
    __syncthreads();
    float mu = rs[0] / DIM;
    float var = rq[0] / DIM - mu*mu;
    float rstd = rsqrtf(var + 1e-5f);
    for (int j = threadIdx.x; j < DIM; j += blockDim.x)
        p[j] = (p[j]-mu)*rstd*w[j] + b[j];
}

// ----- gating scale pass: out_row *= (1 + gamma*sigmoid(dot[row])) -----------
__global__ void mask_scale_kernel(float* __restrict__ out,
                                  const float* __restrict__ dotp,
                                  const float* __restrict__ gamma)
{
    const int t = blockIdx.x;
    const int b = t / NTOK, r = t - b*NTOK;
    const float sc = 1.f + gamma[0] / (1.f + expf(-dotp[t]));
    float4* p = reinterpret_cast<float4*>(out + ((long)b*NTOT + 1 + r)*DIM);
    const int j = threadIdx.x;                // blockDim = 192 = DIM/4
    float4 v = p[j];
    v.x *= sc; v.y *= sc; v.z *= sc; v.w *= sc;
    p[j] = v;
}

__global__ void copy_cls_kernel(const float* __restrict__ img, float* __restrict__ out)
{
    long base = (long)blockIdx.x * NTOT * DIM;
    for (int j = threadIdx.x; j < DIM; j += blockDim.x)
        out[base + j] = img[base + j];
}

// =====================================================================
extern "C" void kernel_launch(void* const* d_in, const int* in_sizes, int n_in,
                              void* d_out, int out_size)
{
    const float* img       = (const float*)d_in[0];
    const float* text      = (const float*)d_in[1];
    const float* w1_msg    = (const float*)d_in[2];
    const float* b1_msg    = (const float*)d_in[3];
    const float* w2_msg    = (const float*)d_in[4];
    const float* b2_msg    = (const float*)d_in[5];
    const float* gamma_gcn = (const float*)d_in[6];
    const float* w1_txt    = (const float*)d_in[7];
    const float* b1_txt    = (const float*)d_in[8];
    const float* w2_txt    = (const float*)d_in[9];
    const float* b2_txt    = (const float*)d_in[10];
    const float* ln_w      = (const float*)d_in[11];
    const float* ln_b      = (const float*)d_in[12];
    const float* gamma     = (const float*)d_in[13];
    float* out = (float*)d_out;

    float *attn, *tq, *dotp;
    __half *attnh, *xh, *xT, *w1T, *w2T, *b1h, *b2h, *texth, *w1tT, *w2tT, *txth;
    cudaGetSymbolAddress((void**)&attn,  g_attn);
    cudaGetSymbolAddress((void**)&attnh, g_attnh);
    cudaGetSymbolAddress((void**)&xh,    g_xh);
    cudaGetSymbolAddress((void**)&xT,    g_xT);
    cudaGetSymbolAddress((void**)&w1T,   g_w1T);
    cudaGetSymbolAddress((void**)&w2T,   g_w2T);
    cudaGetSymbolAddress((void**)&b1h,   g_b1h);
    cudaGetSymbolAddress((void**)&b2h,   g_b2h);
    cudaGetSymbolAddress((void**)&texth, g_texth);
    cudaGetSymbolAddress((void**)&w1tT,  g_w1tT);
    cudaGetSymbolAddress((void**)&w2tT,  g_w2tT);
    cudaGetSymbolAddress((void**)&txth,  g_txth);
    cudaGetSymbolAddress((void**)&tq,    g_tq);
    cudaGetSymbolAddress((void**)&dotp,  g_dot);

    // opt-in >48KB dynamic smem (idempotent; no allocation)
    cudaFuncSetAttribute(hgemm_nt<0>, cudaFuncAttributeMaxDynamicSharedMemorySize, HG_SMEM);
    cudaFuncSetAttribute(hgemm_nt<1>, cudaFuncAttributeMaxDynamicSharedMemorySize, HG_SMEM);
    cudaFuncSetAttribute(hgemm_nt<2>, cudaFuncAttributeMaxDynamicSharedMemorySize, HG_SMEM);
    cudaFuncSetAttribute(hgemm_nt<3>, cudaFuncAttributeMaxDynamicSharedMemorySize, HG_SMEM);
    cudaFuncSetAttribute(hgemm_nt<4>, cudaFuncAttributeMaxDynamicSharedMemorySize, HG_SMEM);

    const float inv_sqrt_d = 0.03608439182435161f;  // 1/sqrt(768)

    // zero the dot accumulator (graph-capturable async memset)
    cudaMemsetAsync(dotp, 0, (size_t)TTOT * sizeof(float));

    // pre-passes
    prep_x_kernel<<<dim3(KPAD/32, DIM/32, BQ), dim3(32, 8)>>>(img, xh, xT);
    transpose_all_kernel<<<dim3(DIM/32, DIM/32, 4), dim3(32, 8)>>>(
        w1_msg, w1T, w2_msg, w2T, w1_txt, w1tT, w2_txt, w2tT);
    conv_text_kernel<<<BQ, DTXT/2>>>(text, texth);

    // 1) scores: S[b] = xh xh^T / sqrt(D)  -> f32 attn
    hgemm_nt<0><<<dim3(2, 2, BQ), 256, HG_SMEM>>>(
        xh, (long)NTOK*DIM, DIM,
        xh, (long)NTOK*DIM, DIM,
        attn, (long)NTOK*NTOK, NTOK,
        NTOK, NTOK, DIM, inv_sqrt_d, nullptr, nullptr, nullptr, nullptr, nullptr);

    // 2) softmax -> half attnh (K-padded)
    softmax_kernel<<<(TTOT*32 + 255)/256, 256>>>(attn, attnh);

    // 3) msg = A @ x -> half b1h
    hgemm_nt<2><<<dim3(6, 2, BQ), 256, HG_SMEM>>>(
        attnh, (long)NTOK*KPAD, KPAD,
        xT, (long)DIM*KPAD, KPAD,
        b1h, (long)NTOK*DIM, DIM,
        NTOK, DIM, KPAD, 1.f, nullptr, nullptr, nullptr, nullptr, nullptr);

    // text branch on the fast path: text1 half gelu, text2 f32, then LN
    hgemm_nt<1><<<dim3(6, 2, 1), 256, HG_SMEM>>>(
        texth, 0, DTXT, w1tT, 0, DTXT, txth, 0, DIM,
        BQ, DIM, DTXT, 1.f, b1_txt, nullptr, nullptr, nullptr, nullptr);
    hgemm_nt<4><<<dim3(6, 2, 1), 256, HG_SMEM>>>(
        txth, 0, DIM, w2tT, 0, DIM, tq, 0, DIM,
        BQ, DIM, DIM, 1.f, b2_txt, nullptr, nullptr, nullptr, nullptr);
    layernorm_kernel<<<BQ, 256>>>(tq, ln_w, ln_b);

    // 4) h = gelu(msg @ w1 + b1) -> half b2h
    hgemm_nt<1><<<dim3(6, TTOT/128, 1), 256, HG_SMEM>>>(
        b1h, 0, DIM, w1T, 0, DIM, b2h, 0, DIM,
        TTOT, DIM, DIM, 1.f, b1_msg, nullptr, nullptr, nullptr, nullptr);

    // 5) x_new = x + gamma_gcn*(h @ w2 + b2) -> f32 d_out (remapped) + dot accum
    hgemm_nt<3><<<dim3(6, TTOT/128, 1), 256, HG_SMEM>>>(
        b2h, 0, DIM, w2T, 0, DIM, out, 0, 0,
        TTOT, DIM, DIM, 1.f, b2_msg, img, gamma_gcn, tq, dotp);

    // cls passthrough + gating scale
    copy_cls_kernel<<<BQ, 256>>>(img, out);
    mask_scale_kernel<<<TTOT, DIM/4>>>(out, dotp, gamma);
}

// round 13
// speedup vs baseline: 2.7434x; 1.1344x over previous
#include <cuda_runtime.h>
#include <cuda_fp16.h>
#include <cstdint>

#define BQ   256
#define NTOK 196
#define NTOT 197
#define DIM  768
#define DTXT 512
#define TTOT (BQ*NTOK)
#define KPAD 224

// ---------------- scratch (device globals) ----------------
__device__ float  g_attn [(size_t)BQ*NTOK*NTOK];
__device__ __half g_attnh[(size_t)BQ*NTOK*KPAD];
__device__ __half g_xh  [(size_t)TTOT*DIM];
__device__ __half g_xT  [(size_t)BQ*DIM*KPAD];
__device__ __half g_w1T [(size_t)DIM*DIM];
__device__ __half g_w2T [(size_t)DIM*DIM];
__device__ __half g_b1h [(size_t)TTOT*DIM];
__device__ __half g_b2h [(size_t)TTOT*DIM];
__device__ __half g_texth[(size_t)BQ*DTXT];
__device__ __half g_w1tT [(size_t)DIM*DTXT];
__device__ __half g_w2tT [(size_t)DIM*DIM];
__device__ __half g_txth [(size_t)BQ*DIM];
__device__ float  g_tq  [(size_t)BQ*DIM];
__device__ float  g_dot [(size_t)TTOT];

__device__ __forceinline__ float gelu_exact(float x) { return x * normcdff(x); }

__device__ __forceinline__ void cp16(uint32_t dst, const void* src, bool ok) {
    int sz = ok ? 16 : 0;
    asm volatile("cp.async.cg.shared.global [%0], [%1], 16, %2;\n"
                 :: "r"(dst), "l"(src), "r"(sz));
}
#define CP_COMMIT() asm volatile("cp.async.commit_group;\n")
#define CP_WAIT2()  asm volatile("cp.async.wait_group 2;\n")

__device__ __forceinline__ void ldsm4(uint32_t& r0, uint32_t& r1,
                                      uint32_t& r2, uint32_t& r3, uint32_t addr) {
    asm volatile("ldmatrix.sync.aligned.m8n8.x4.shared.b16 {%0,%1,%2,%3}, [%4];"
                 : "=r"(r0), "=r"(r1), "=r"(r2), "=r"(r3) : "r"(addr));
}

// =====================================================================
// fp16 NT GEMM via mma.sync: C = alpha*A(MxK)*B(NxK)^T
// A,B row-major half, K%32==0, rows 16B aligned. 128x128x32 tile,
// 8 warps (warp 64x32), 4-stage cp.async pipeline (wait_group 2),
// dynamic smem 64KB, swizzled tiles, ldmatrix fragment loads.
// MODE 0: f32 C = alpha*acc                       (scores; M,N guards)
// MODE 2: half C = acc                            (msg; M guard)
// MODE 1: half C = gelu(acc+bias)                 (mlp1/text1; exact tiles)
// MODE 4: f32 C = acc + bias                      (text2; exact tiles)
// MODE 3: f32 out[remap]=resid[remap]+g*(acc+bias) + dot accum (mlp2)
// =====================================================================
#define HG_SMEM 65536
#define NSTG 4

template<int MODE>
__launch_bounds__(256, 2)
__global__ void hgemm_nt(const __half* __restrict__ A, long aBS, int lda,
                         const __half* __restrict__ B, long bBS, int ldb,
                         void* __restrict__ Cv, long cBS, int ldc,
                         int M, int N, int K, float alpha,
                         const float* __restrict__ bias,
                         const float* __restrict__ resid,
                         const float* __restrict__ gscale,
                         const float* __restrict__ tq,
                         float* __restrict__ dotp)
{
    extern __shared__ uint32_t smem_dyn[];
    uint32_t* As = smem_dyn;                    // NSTG x 2048 u32
    uint32_t* Bs = smem_dyn + NSTG * 2048;      // NSTG x 2048 u32

    const int tid  = threadIdx.x;
    const int lane = tid & 31;
    const int wid  = tid >> 5;
    const int wm   = wid & 1;
    const int wn   = wid >> 1;
    const int m0   = blockIdx.y * 128;
    const int n0   = blockIdx.x * 128;

    const __half* Ab = A + (long)blockIdx.z * aBS;
    const __half* Bb = B + (long)blockIdx.z * bBS;

    const uint32_t asb = (uint32_t)__cvta_generic_to_shared(As);
    const uint32_t bsb = (uint32_t)__cvta_generic_to_shared(Bs);

    float acc[4][4][4];
    #pragma unroll
    for (int i = 0; i < 4; i++)
        #pragma unroll
        for (int j = 0; j < 4; j++)
            #pragma unroll
            for (int r = 0; r < 4; r++) acc[i][j][r] = 0.f;

    // ---- cp.async loader geometry ----
    const int ld_r  = tid >> 1;
    const int ld_hs = tid & 1;
    const int ld_sw = (ld_r >> 1) & 3;
    const int gA    = ((ld_hs*2 + 0) ^ ld_sw) << 2;
    const int gB    = ((ld_hs*2 + 1) ^ ld_sw) << 2;
    const bool okA  = (m0 + ld_r) < M;
    const bool okB  = (n0 + ld_r) < N;
    const __half* pa = Ab + (long)(okA ? (m0 + ld_r) : 0) * lda + ld_hs*16;
    const __half* pb = Bb + (long)(okB ? (n0 + ld_r) : 0) * ldb + ld_hs*16;
    const uint32_t dA0 = asb + (uint32_t)(ld_r*16 + gA) * 4;
    const uint32_t dA1 = asb + (uint32_t)(ld_r*16 + gB) * 4;
    const uint32_t dB0 = bsb + (uint32_t)(ld_r*16 + gA) * 4;
    const uint32_t dB1 = bsb + (uint32_t)(ld_r*16 + gB) * 4;

    auto load_stage = [&](int st, int k0) {
        const uint32_t so = (uint32_t)(st * 2048 * 4);
        cp16(dA0 + so, pa + k0,     okA);
        cp16(dA1 + so, pa + k0 + 8, okA);
        cp16(dB0 + so, pb + k0,     okB);
        cp16(dB1 + so, pb + k0 + 8, okB);
    };

    const int NIT = K / 32;
    load_stage(0, 0); CP_COMMIT();
    if (NIT > 1) load_stage(1, 32);
    CP_COMMIT();
    if (NIT > 2) load_stage(2, 64);
    CP_COMMIT();

    // ---- ldmatrix per-lane base addresses (stage 0, ks 0) ----
    // A tile i: lanes 0-7 rows m+0..7 (k-seg0), 8-15 rows m+8..15 (seg0),
    //           16-23 rows m+0..7 (seg1), 24-31 rows m+8..15 (seg1)
    uint32_t aAddr[4];
    {
        const int r_lo = (lane & 7) + ((lane >> 3) & 1) * 8;
        const int grp  = lane >> 4;                     // k 16B-seg 0/1
        #pragma unroll
        for (int i = 0; i < 4; i++) {
            const int row = wm*64 + i*16 + r_lo;
            aAddr[i] = asb + (uint32_t)(row*64 + 16*(grp ^ ((row >> 1) & 3)));
        }
    }
    // B pair p (n-tiles 2p, 2p+1): lanes 0-7 rows n(2p)+0..7 seg0,
    //   8-15 rows n(2p) seg1, 16-23 rows n(2p+1) seg0, 24-31 n(2p+1) seg1
    uint32_t bAddr[2];
    {
        const int grp = (lane >> 3) & 1;
        #pragma unroll
        for (int p = 0; p < 2; p++) {
            const int row = wn*32 + p*16 + (lane >> 4) * 8 + (lane & 7);
            bAddr[p] = bsb + (uint32_t)(row*64 + 16*(grp ^ ((row >> 1) & 3)));
        }
    }

    uint32_t soff = 0;
    for (int it = 0; it < NIT; it++) {
        CP_WAIT2();
        __syncthreads();
        if (it + 3 < NIT) load_stage((it + 3) & (NSTG-1), (it + 3) * 32);
        CP_COMMIT();

        #pragma unroll
        for (int ks = 0; ks < 2; ks++) {
            const uint32_t kx = (uint32_t)(ks * 32);   // swizzle-safe k-seg XOR
            uint32_t af[4][4];
            #pragma unroll
            for (int i = 0; i < 4; i++)
                ldsm4(af[i][0], af[i][1], af[i][2], af[i][3],
                      (aAddr[i] + soff) ^ kx);
            uint32_t bf[4][2];
            #pragma unroll
            for (int p = 0; p < 2; p++)
                ldsm4(bf[2*p][0], bf[2*p][1], bf[2*p+1][0], bf[2*p+1][1],
                      (bAddr[p] + soff) ^ kx);
            #pragma unroll
            for (int i = 0; i < 4; i++)
                #pragma unroll
                for (int j = 0; j < 4; j++) {
                    asm volatile(
                        "mma.sync.aligned.m16n8k16.row.col.f32.f16.f16.f32 "
                        "{%0,%1,%2,%3}, {%4,%5,%6,%7}, {%8,%9}, {%0,%1,%2,%3};\n"
                        : "+f"(acc[i][j][0]), "+f"(acc[i][j][1]),
                          "+f"(acc[i][j][2]), "+f"(acc[i][j][3])
                        : "r"(af[i][0]), "r"(af[i][1]), "r"(af[i][2]), "r"(af[i][3]),
                          "r"(bf[j][0]), "r"(bf[j][1]));
                }
        }
        soff = (soff + 8192u) & (uint32_t)(NSTG * 8192 - 1);
    }

    // ---------------- epilogue ----------------
    const int g = lane >> 2;
    const int tg = lane & 3;

    if (MODE == 0) {            // scores: f32 = alpha*acc, M/N guards
        float* Cf = reinterpret_cast<float*>(Cv) + (long)blockIdx.z * cBS;
        #pragma unroll
        for (int i = 0; i < 4; i++)
            #pragma unroll
            for (int hi = 0; hi < 2; hi++) {
                const int row = m0 + wm*64 + i*16 + g + 8*hi;
                if (row >= M) continue;
                #pragma unroll
                for (int j = 0; j < 4; j++) {
                    const int col = n0 + wn*32 + j*8 + tg*2;
                    if (col >= N) continue;
                    float2 o = make_float2(acc[i][j][2*hi+0] * alpha,
                                           acc[i][j][2*hi+1] * alpha);
                    *reinterpret_cast<float2*>(Cf + (long)row*ldc + col) = o;
                }
            }
    } else if (MODE == 2) {     // msg: half = acc, M guard only
        __half* Ch = reinterpret_cast<__half*>(Cv) + (long)blockIdx.z * cBS;
        #pragma unroll
        for (int i = 0; i < 4; i++)
            #pragma unroll
            for (int hi = 0; hi < 2; hi++) {
                const int row = m0 + wm*64 + i*16 + g + 8*hi;
                if (row >= M) continue;
                #pragma unroll
                for (int j = 0; j < 4; j++) {
                    const int col = n0 + wn*32 + j*8 + tg*2;
                    *reinterpret_cast<__half2*>(Ch + (long)row*ldc + col) =
                        __floats2half2_rn(acc[i][j][2*hi+0], acc[i][j][2*hi+1]);
                }
            }
    } else if (MODE == 1) {     // half = gelu(acc+bias), exact tiles
        __half* Ch = reinterpret_cast<__half*>(Cv);
        #pragma unroll
        for (int i = 0; i < 4; i++)
            #pragma unroll
            for (int hi = 0; hi < 2; hi++) {
                const int row = m0 + wm*64 + i*16 + g + 8*hi;
                #pragma unroll
                for (int j = 0; j < 4; j++) {
                    const int col = n0 + wn*32 + j*8 + tg*2;
                    float v0 = gelu_exact(acc[i][j][2*hi+0] + bias[col]);
                    float v1 = gelu_exact(acc[i][j][2*hi+1] + bias[col+1]);
                    *reinterpret_cast<__half2*>(Ch + (long)row*ldc + col) =
                        __floats2half2_rn(v0, v1);
                }
            }
    } else if (MODE == 4) {     // f32 = acc + bias, exact tiles
        float* Cf = reinterpret_cast<float*>(Cv);
        #pragma unroll
        for (int i = 0; i < 4; i++)
            #pragma unroll
            for (int hi = 0; hi < 2; hi++) {
                const int row = m0 + wm*64 + i*16 + g + 8*hi;
                #pragma unroll
                for (int j = 0; j < 4; j++) {
                    const int col = n0 + wn*32 + j*8 + tg*2;
                    float2 o = make_float2(acc[i][j][2*hi+0] + bias[col],
                                           acc[i][j][2*hi+1] + bias[col+1]);
                    *reinterpret_cast<float2*>(Cf + (long)row*ldc + col) = o;
                }
            }
    } else {                    // mlp2: residual+remap + dot accumulation
        float* Cf = reinterpret_cast<float*>(Cv);
        const float gsc = gscale[0];
        #pragma unroll
        for (int i = 0; i < 4; i++)
            #pragma unroll
            for (int hi = 0; hi < 2; hi++) {
                const int row = m0 + wm*64 + i*16 + g + 8*hi;   // token index
                const int b   = row / NTOK;
                const int rr  = row - b * NTOK;
                const long off = ((long)b * NTOT + 1 + rr) * DIM;
                const float* tqr = tq + (long)b * DIM;
                float part = 0.f;
                #pragma unroll
                for (int j = 0; j < 4; j++) {
                    const int col = n0 + wn*32 + j*8 + tg*2;
                    float2 rv = *reinterpret_cast<const float2*>(resid + off + col);
                    float2 tv = *reinterpret_cast<const float2*>(tqr + col);
                    float o0 = rv.x + gsc * (acc[i][j][2*hi+0] + bias[col]);
                    float o1 = rv.y + gsc * (acc[i][j][2*hi+1] + bias[col+1]);
                    *reinterpret_cast<float2*>(Cf + off + col) = make_float2(o0, o1);
                    part += o0 * tv.x + o1 * tv.y;
                }
                part += __shfl_xor_sync(0xffffffffu, part, 1);
                part += __shfl_xor_sync(0xffffffffu, part, 2);
                if (tg == 0) atomicAdd(dotp + row, part);
            }
    }
}

// ------- fused pre-pass: img tokens -> xh (row-major half) + xT (half^T) -----
__global__ void prep_x_kernel(const float* __restrict__ img,
                              __half* __restrict__ xh, __half* __restrict__ xT)
{
    __shared__ float tile[32][33];
    const int b  = blockIdx.z;
    const int t0 = blockIdx.x * 32;
    const int d0 = blockIdx.y * 32;
    #pragma unroll
    for (int i = threadIdx.y; i < 32; i += 8) {
        const int t = t0 + i;
        float v = 0.f;
        if (t < NTOK) {
            v = img[((long)b*NTOT + 1 + t)*DIM + d0 + threadIdx.x];
            xh[((long)b*NTOK + t)*DIM + d0 + threadIdx.x] = __float2half_rn(v);
        }
        tile[i][threadIdx.x] = v;
    }
    __syncthreads();
    #pragma unroll
    for (int i = threadIdx.y; i < 32; i += 8) {
        const int d = d0 + i;
        xT[((long)b*DIM + d)*KPAD + t0 + threadIdx.x] =
            __float2half_rn(tile[threadIdx.x][i]);
    }
}

// ----- pre-pass: all 4 weight transposes in one launch (z selects matrix) ----
__global__ void transpose_all_kernel(
    const float* __restrict__ w1m, __half* __restrict__ w1mT,
    const float* __restrict__ w2m, __half* __restrict__ w2mT,
    const float* __restrict__ w1t, __half* __restrict__ w1tT,
    const float* __restrict__ w2t, __half* __restrict__ w2tT)
{
    __shared__ float tile[32][33];
    const float* W; __half* WT; int R;
    switch (blockIdx.z) {
        case 0:  W = w1m; WT = w1mT; R = DIM;  break;
        case 1:  W = w2m; WT = w2mT; R = DIM;  break;
        case 2:  W = w1t; WT = w1tT; R = DTXT; break;
        default: W = w2t; WT = w2tT; R = DIM;  break;
    }
    const int k0 = blockIdx.x * 32;
    if (k0 >= R) return;
    const int n0 = blockIdx.y * 32;
    #pragma unroll
    for (int i = threadIdx.y; i < 32; i += 8)
        tile[i][threadIdx.x] = W[(long)(k0+i)*DIM + n0 + threadIdx.x];
    __syncthreads();
    #pragma unroll
    for (int i = threadIdx.y; i < 32; i += 8)
        WT[(long)(n0+i)*R + k0 + threadIdx.x] = __float2half_rn(tile[threadIdx.x][i]);
}

// ---------------- pre-pass: text f32 -> half ---------------------------------
__global__ void conv_text_kernel(const float* __restrict__ text, __half* __restrict__ th)
{
    const long base = (long)blockIdx.x * DTXT;
    const float2* src = reinterpret_cast<const float2*>(text + base);
    __half2* dst = reinterpret_cast<__half2*>(th + base);
    dst[threadIdx.x] = __float22half2_rn(src[threadIdx.x]);
}

// ------- softmax rows of g_attn -> half g_attnh (stride KPAD, zero-pad) -----
__global__ void softmax_kernel(const float* __restrict__ S, __half* __restrict__ Sh)
{
    int warp = (blockIdx.x * blockDim.x + threadIdx.x) >> 5;
    int lane = threadIdx.x & 31;
    if (warp >= (int)(BQ * NTOK)) return;
    const float* p = S + (long)warp * NTOK;
    __half* ph = Sh + (long)warp * KPAD;

    float v[7], mx = -3.0e38f;
    #pragma unroll
    for (int it = 0; it < 7; it++) {
        int j = lane + it*32;
        v[it] = (j < NTOK) ? p[j] : -3.0e38f;
        mx = fmaxf(mx, v[it]);
    }
    #pragma unroll
    for (int o = 16; o; o >>= 1) mx = fmaxf(mx, __shfl_xor_sync(0xffffffffu, mx, o));
    float s = 0.f;
    #pragma unroll
    for (int it = 0; it < 7; it++) {
        int j = lane + it*32;
        if (j < NTOK) { v[it] = expf(v[it]-mx); s += v[it]; } else v[it] = 0.f;
    }
    #pragma unroll
    for (int o = 16; o; o >>= 1) s += __shfl_xor_sync(0xffffffffu, s, o);
    float inv = 1.f / s;
    #pragma unroll
    for (int it = 0; it < 7; it++) {
        int j = lane + it*32;
        ph[j] = __float2half_rn((j < NTOK) ? v[it]*inv : 0.f);
    }
}

__global__ void layernorm_kernel(float* __restrict__ X,
                                 const float* __restrict__ w,
                                 const float* __restrict__ b)
{
    int row = blockIdx.x;
    float* p = X + (long)row * DIM;
    float s = 0.f, sq = 0.f;
    for (int j = threadIdx.x; j < DIM; j += blockDim.x) {
        float x = p[j]; s += x; sq += x*x;
    }
    __shared__ float rs[32], rq[32];
    int lane = threadIdx.x & 31, wd = threadIdx.x >> 5;
    #pragma unroll
    for (int o = 16; o; o >>= 1) {
        s  += __shfl_xor_sync(0xffffffffu, s, o);
        sq += __shfl_xor_sync(0xffffffffu, sq, o);
    }
    if (lane == 0) { rs[wd] = s; rq[wd] = sq; }
    __syncthreads();
    int nw = blockDim.x >> 5;
    if (wd == 0) {
        float a = (lane < nw) ? rs[lane] : 0.f;
        float cc = (lane < nw) ? rq[lane] : 0.f;
        #pragma unroll
        for (int o = 16; o; o >>= 1) {
            a  += __shfl_xor_sync(0xffffffffu, a, o);
            cc += __shfl_xor_sync(0xffffffffu, cc, o);
        }
        if (lane == 0) { rs[0] = a; rq[0] = cc; }
    }
    __syncthreads();
    float mu = rs[0] / DIM;
    float var = rq[0] / DIM - mu*mu;
    float rstd = rsqrtf(var + 1e-5f);
    for (int j = threadIdx.x; j < DIM; j += blockDim.x)
        p[j] = (p[j]-mu)*rstd*w[j] + b[j];
}

// ----- gating scale pass: out_row *= (1 + gamma*sigmoid(dot[row])) -----------
__global__ void mask_scale_kernel(float* __restrict__ out,
                                  const float* __restrict__ dotp,
                                  const float* __restrict__ gamma)
{
    const int t = blockIdx.x;
    const int b = t / NTOK, r = t - b*NTOK;
    const float sc = 1.f + gamma[0] / (1.f + expf(-dotp[t]));
    float4* p = reinterpret_cast<float4*>(out + ((long)b*NTOT + 1 + r)*DIM);
    const int j = threadIdx.x;                // blockDim = 192 = DIM/4
    float4 v = p[j];
    v.x *= sc; v.y *= sc; v.z *= sc; v.w *= sc;
    p[j] = v;
}

__global__ void copy_cls_kernel(const float* __restrict__ img, float* __restrict__ out)
{
    long base = (long)blockIdx.x * NTOT * DIM;
    for (int j = threadIdx.x; j < DIM; j += blockDim.x)
        out[base + j] = img[base + j];
}

// =====================================================================
extern "C" void kernel_launch(void* const* d_in, const int* in_sizes, int n_in,
                              void* d_out, int out_size)
{
    const float* img       = (const float*)d_in[0];
    const float* text      = (const float*)d_in[1];
    const float* w1_msg    = (const float*)d_in[2];
    const float* b1_msg    = (const float*)d_in[3];
    const float* w2_msg    = (const float*)d_in[4];
    const float* b2_msg    = (const float*)d_in[5];
    const float* gamma_gcn = (const float*)d_in[6];
    const float* w1_txt    = (const float*)d_in[7];
    const float* b1_txt    = (const float*)d_in[8];
    const float* w2_txt    = (const float*)d_in[9];
    const float* b2_txt    = (const float*)d_in[10];
    const float* ln_w      = (const float*)d_in[11];
    const float* ln_b      = (const float*)d_in[12];
    const float* gamma     = (const float*)d_in[13];
    float* out = (float*)d_out;

    float *attn, *tq, *dotp;
    __half *attnh, *xh, *xT, *w1T, *w2T, *b1h, *b2h, *texth, *w1tT, *w2tT, *txth;
    cudaGetSymbolAddress((void**)&attn,  g_attn);
    cudaGetSymbolAddress((void**)&attnh, g_attnh);
    cudaGetSymbolAddress((void**)&xh,    g_xh);
    cudaGetSymbolAddress((void**)&xT,    g_xT);
    cudaGetSymbolAddress((void**)&w1T,   g_w1T);
    cudaGetSymbolAddress((void**)&w2T,   g_w2T);
    cudaGetSymbolAddress((void**)&b1h,   g_b1h);
    cudaGetSymbolAddress((void**)&b2h,   g_b2h);
    cudaGetSymbolAddress((void**)&texth, g_texth);
    cudaGetSymbolAddress((void**)&w1tT,  g_w1tT);
    cudaGetSymbolAddress((void**)&w2tT,  g_w2tT);
    cudaGetSymbolAddress((void**)&txth,  g_txth);
    cudaGetSymbolAddress((void**)&tq,    g_tq);
    cudaGetSymbolAddress((void**)&dotp,  g_dot);

    cudaFuncSetAttribute(hgemm_nt<0>, cudaFuncAttributeMaxDynamicSharedMemorySize, HG_SMEM);
    cudaFuncSetAttribute(hgemm_nt<1>, cudaFuncAttributeMaxDynamicSharedMemorySize, HG_SMEM);
    cudaFuncSetAttribute(hgemm_nt<2>, cudaFuncAttributeMaxDynamicSharedMemorySize, HG_SMEM);
    cudaFuncSetAttribute(hgemm_nt<3>, cudaFuncAttributeMaxDynamicSharedMemorySize, HG_SMEM);
    cudaFuncSetAttribute(hgemm_nt<4>, cudaFuncAttributeMaxDynamicSharedMemorySize, HG_SMEM);

    const float inv_sqrt_d = 0.03608439182435161f;  // 1/sqrt(768)

    cudaMemsetAsync(dotp, 0, (size_t)TTOT * sizeof(float));

    // pre-passes
    prep_x_kernel<<<dim3(KPAD/32, DIM/32, BQ), dim3(32, 8)>>>(img, xh, xT);
    transpose_all_kernel<<<dim3(DIM/32, DIM/32, 4), dim3(32, 8)>>>(
        w1_msg, w1T, w2_msg, w2T, w1_txt, w1tT, w2_txt, w2tT);
    conv_text_kernel<<<BQ, DTXT/2>>>(text, texth);

    // 1) scores: S[b] = xh xh^T / sqrt(D)  -> f32 attn
    hgemm_nt<0><<<dim3(2, 2, BQ), 256, HG_SMEM>>>(
        xh, (long)NTOK*DIM, DIM,
        xh, (long)NTOK*DIM, DIM,
        attn, (long)NTOK*NTOK, NTOK,
        NTOK, NTOK, DIM, inv_sqrt_d, nullptr, nullptr, nullptr, nullptr, nullptr);

    // 2) softmax -> half attnh (K-padded)
    softmax_kernel<<<(TTOT*32 + 255)/256, 256>>>(attn, attnh);

    // 3) msg = A @ x -> half b1h
    hgemm_nt<2><<<dim3(6, 2, BQ), 256, HG_SMEM>>>(
        attnh, (long)NTOK*KPAD, KPAD,
        xT, (long)DIM*KPAD, KPAD,
        b1h, (long)NTOK*DIM, DIM,
        NTOK, DIM, KPAD, 1.f, nullptr, nullptr, nullptr, nullptr, nullptr);

    // text branch on the fast path
    hgemm_nt<1><<<dim3(6, 2, 1), 256, HG_SMEM>>>(
        texth, 0, DTXT, w1tT, 0, DTXT, txth, 0, DIM,
        BQ, DIM, DTXT, 1.f, b1_txt, nullptr, nullptr, nullptr, nullptr);
    hgemm_nt<4><<<dim3(6, 2, 1), 256, HG_SMEM>>>(
        txth, 0, DIM, w2tT, 0, DIM, tq, 0, DIM,
        BQ, DIM, DIM, 1.f, b2_txt, nullptr, nullptr, nullptr, nullptr);
    layernorm_kernel<<<BQ, 256>>>(tq, ln_w, ln_b);

    // 4) h = gelu(msg @ w1 + b1) -> half b2h
    hgemm_nt<1><<<dim3(6, TTOT/128, 1), 256, HG_SMEM>>>(
        b1h, 0, DIM, w1T, 0, DIM, b2h, 0, DIM,
        TTOT, DIM, DIM, 1.f, b1_msg, nullptr, nullptr, nullptr, nullptr);

    // 5) x_new = x + gamma_gcn*(h @ w2 + b2) -> f32 d_out (remapped) + dot accum
    hgemm_nt<3><<<dim3(6, TTOT/128, 1), 256, HG_SMEM>>>(
        b2h, 0, DIM, w2T, 0, DIM, out, 0, 0,
        TTOT, DIM, DIM, 1.f, b2_msg, img, gamma_gcn, tq, dotp);

    // cls passthrough + gating scale
    copy_cls_kernel<<<BQ, 256>>>(img, out);
    mask_scale_kernel<<<TTOT, DIM/4>>>(out, dotp, gamma);
}